// round 1
// baseline (speedup 1.0000x reference)
#include <cuda_runtime.h>
#include <math.h>

#define NN 50000
#define NE 500000
#define HID 256
#define NLAYERS 15
#define EPSV 1e-5f

// ---------------- scratch (device globals: allocation-free) ----------------
__device__ float g_h[(size_t)NN * HID];    // node features (residual stream)
__device__ float g_agg[(size_t)NN * HID];  // neighborhood sums
__device__ float g_out[(size_t)NN * HID];  // pre-BN layer output
__device__ float g_z1[(size_t)NE * HID];   // edge MLP hidden 1
__device__ float g_z2[(size_t)NE * HID];   // edge MLP hidden 2
__device__ int   g_rowptr[NN + 1];
__device__ int   g_cnt[NN];
__device__ int   g_col[NE];                // src node per CSR slot (sorted by dst)
__device__ float g_bnsum[HID];
__device__ float g_bnsq[HID];
__device__ float g_scale[HID];
__device__ float g_shift[HID];

// ---------------- input fc: h = x @ W_in^T  (IN_CH = 2) ----------------
__global__ void k_input(const float* __restrict__ x, const float* __restrict__ W_in) {
    int i = blockIdx.x;
    int c = threadIdx.x;
    if (i < NN) {
        float x0 = x[2 * i], x1 = x[2 * i + 1];
        g_h[(size_t)i * HID + c] = x0 * W_in[2 * c] + x1 * W_in[2 * c + 1];
    }
}

// ---------------- CSR build ----------------
__global__ void k_zero_cnt() {
    int i = blockIdx.x * blockDim.x + threadIdx.x;
    if (i < NN) g_cnt[i] = 0;
}

__global__ void k_count(const int* __restrict__ dst) {
    int i = blockIdx.x * blockDim.x + threadIdx.x;
    if (i < NE) atomicAdd(&g_cnt[dst[i]], 1);
}

// single-block exclusive scan over g_cnt -> g_rowptr
__global__ void k_scan() {
    __shared__ int s[1024];
    int t = threadIdx.x;
    const int CH = (NN + 1023) / 1024;  // 49
    int base = t * CH;
    int loc = 0;
    for (int j = 0; j < CH; j++) {
        int i = base + j;
        if (i < NN) loc += g_cnt[i];
    }
    s[t] = loc;
    __syncthreads();
    for (int off = 1; off < 1024; off <<= 1) {
        int v = 0;
        if (t >= off) v = s[t - off];
        __syncthreads();
        s[t] += v;
        __syncthreads();
    }
    int run = (t == 0) ? 0 : s[t - 1];
    for (int j = 0; j < CH; j++) {
        int i = base + j;
        if (i < NN) { g_rowptr[i] = run; run += g_cnt[i]; }
    }
    if (t == 0) g_rowptr[NN] = s[1023];
}

__global__ void k_fill(const int* __restrict__ src, const int* __restrict__ dst) {
    int i = blockIdx.x * blockDim.x + threadIdx.x;
    if (i < NE) {
        int d = dst[i];
        int p = atomicAdd(&g_cnt[d], 1);
        g_col[g_rowptr[d] + p] = src[i];
    }
}

// ---------------- aggregation: agg[i] = sum over in-edges of h[src] ----------------
// warp per node, each lane owns 8 channels (2 float4)
__global__ void k_agg() {
    int w = (blockIdx.x * blockDim.x + threadIdx.x) >> 5;
    int lane = threadIdx.x & 31;
    if (w >= NN) return;
    int e0 = g_rowptr[w], e1 = g_rowptr[w + 1];
    float4 a0 = make_float4(0.f, 0.f, 0.f, 0.f);
    float4 a1 = make_float4(0.f, 0.f, 0.f, 0.f);
    for (int e = e0; e < e1; e++) {
        int s = g_col[e];
        const float4* hp = (const float4*)(g_h + (size_t)s * HID);
        float4 b0 = hp[lane];
        float4 b1 = hp[lane + 32];
        a0.x += b0.x; a0.y += b0.y; a0.z += b0.z; a0.w += b0.w;
        a1.x += b1.x; a1.y += b1.y; a1.z += b1.z; a1.w += b1.w;
    }
    float4* ap = (float4*)(g_agg + (size_t)w * HID);
    ap[lane] = a0;
    ap[lane + 32] = a1;
}

// ---------------- dual-operand SGEMM ----------------
// C[M, 256] = A1 @ B1^T (+ A2 @ B2^T) + bias, optional row-gather on A, optional relu.
// B rows are [N=256, K] row-major with row stride ldb. K per half = 256.
// MODE 0: A1=g_agg/B1=Wrel, A2=g_h/B2=Wroot, C=g_out, no relu
// MODE 1: A1=g_h gather src, A2=g_h gather dst (B=W1 halves, ldb=512), C=g_z1, relu
// MODE 2: A1=g_z1, single half (B=W2), C=g_z2, relu
template <int MODE>
__global__ __launch_bounds__(256, 2) void k_gemm(
    const float* __restrict__ B1, const float* __restrict__ B2, int ldb,
    const float* __restrict__ bias, const int* __restrict__ idx1,
    const int* __restrict__ idx2, int M)
{
    constexpr int BM = 128, BN = 128, BK = 8;
    constexpr bool RELU = (MODE != 0);
    constexpr bool GATHER = (MODE == 1);
    constexpr int NH = (MODE == 2) ? 1 : 2;

    const float* A1 = (MODE == 0) ? g_agg : ((MODE == 1) ? g_h : g_z1);
    const float* A2 = (MODE == 2) ? (const float*)0 : g_h;
    float* C = (MODE == 0) ? g_out : ((MODE == 1) ? g_z1 : g_z2);

    __shared__ float As[BK][BM + 4];
    __shared__ float Bs[BK][BN + 4];
    __shared__ int rix[BM];

    int tid = threadIdx.x;
    int tx = tid & 15;      // 0..15 -> 8 cols each
    int ty = tid >> 4;      // 0..15 -> 8 rows each
    int m0 = blockIdx.x * BM;
    int n0 = blockIdx.y * BN;

    float acc[8][8];
#pragma unroll
    for (int i = 0; i < 8; i++)
#pragma unroll
        for (int j = 0; j < 8; j++) acc[i][j] = 0.f;

    int lrow = tid >> 1;          // 0..127
    int lc4 = (tid & 1) * 4;      // 0 or 4

    for (int hf = 0; hf < NH; hf++) {
        const float* A = hf ? A2 : A1;
        const float* B = hf ? B2 : B1;
        if (GATHER) {
            const int* idx = hf ? idx2 : idx1;
            __syncthreads();
            if (tid < BM) {
                int gm = m0 + tid;
                rix[tid] = (gm < M) ? idx[gm] : 0;
            }
            __syncthreads();
        }
        for (int kb = 0; kb < HID; kb += BK) {
            // A tile: 128 rows x 8 k, transposed into As[k][m]
            float4 av = make_float4(0.f, 0.f, 0.f, 0.f);
            int gm = m0 + lrow;
            if (gm < M) {
                size_t ar = GATHER ? (size_t)rix[lrow] * HID : (size_t)gm * HID;
                av = *(const float4*)(A + ar + kb + lc4);
            }
            As[lc4 + 0][lrow] = av.x;
            As[lc4 + 1][lrow] = av.y;
            As[lc4 + 2][lrow] = av.z;
            As[lc4 + 3][lrow] = av.w;
            // B tile: 128 n-rows x 8 k, transposed into Bs[k][n]  (n0+lrow < 256 always)
            float4 bv = *(const float4*)(B + (size_t)(n0 + lrow) * ldb + kb + lc4);
            Bs[lc4 + 0][lrow] = bv.x;
            Bs[lc4 + 1][lrow] = bv.y;
            Bs[lc4 + 2][lrow] = bv.z;
            Bs[lc4 + 3][lrow] = bv.w;
            __syncthreads();
#pragma unroll
            for (int k = 0; k < BK; k++) {
                float a[8], b[8];
#pragma unroll
                for (int i = 0; i < 8; i++) a[i] = As[k][ty * 8 + i];
#pragma unroll
                for (int j = 0; j < 8; j++) b[j] = Bs[k][tx * 8 + j];
#pragma unroll
                for (int i = 0; i < 8; i++)
#pragma unroll
                    for (int j = 0; j < 8; j++) acc[i][j] += a[i] * b[j];
            }
            __syncthreads();
        }
    }

    float bsv[8];
#pragma unroll
    for (int j = 0; j < 8; j++) bsv[j] = bias[n0 + tx * 8 + j];
#pragma unroll
    for (int i = 0; i < 8; i++) {
        int gm = m0 + ty * 8 + i;
        if (gm < M) {
#pragma unroll
            for (int j = 0; j < 8; j++) {
                float c = acc[i][j] + bsv[j];
                if (RELU) c = fmaxf(c, 0.f);
                acc[i][j] = c;
            }
            float4* cp = (float4*)(C + (size_t)gm * HID + n0 + tx * 8);
            cp[0] = make_float4(acc[i][0], acc[i][1], acc[i][2], acc[i][3]);
            cp[1] = make_float4(acc[i][4], acc[i][5], acc[i][6], acc[i][7]);
        }
    }
}

// ---------------- batchnorm ----------------
__global__ void k_bnzero() {
    int c = threadIdx.x;
    g_bnsum[c] = 0.f;
    g_bnsq[c] = 0.f;
}

__global__ void k_bnstat() {
    int c = threadIdx.x;           // channel
    int r0 = blockIdx.x * 250;     // 200 blocks x 250 rows = 50000
    float s = 0.f, q = 0.f;
    for (int r = 0; r < 250; r++) {
        float v = g_out[(size_t)(r0 + r) * HID + c];
        s += v;
        q += v * v;
    }
    atomicAdd(&g_bnsum[c], s);
    atomicAdd(&g_bnsq[c], q);
}

__global__ void k_bnfin(const float* __restrict__ gamma, const float* __restrict__ beta) {
    int c = threadIdx.x;
    float mean = g_bnsum[c] * (1.f / NN);
    float var = g_bnsq[c] * (1.f / NN) - mean * mean;
    float inv = rsqrtf(var + EPSV);
    float sc = gamma[c] * inv;
    g_scale[c] = sc;
    g_shift[c] = beta[c] - mean * sc;
}

// h += relu(out * scale + shift)
__global__ void k_update() {
    int i = blockIdx.x * blockDim.x + threadIdx.x;  // over NN*64 float4s
    if (i >= NN * (HID / 4)) return;
    int c4 = (i & (HID / 4 - 1)) * 4;
    float4 o = ((const float4*)g_out)[i];
    float4 sc = *(const float4*)(g_scale + c4);
    float4 sh = *(const float4*)(g_shift + c4);
    float4 h = ((const float4*)g_h)[i];
    h.x += fmaxf(o.x * sc.x + sh.x, 0.f);
    h.y += fmaxf(o.y * sc.y + sh.y, 0.f);
    h.z += fmaxf(o.z * sc.z + sh.z, 0.f);
    h.w += fmaxf(o.w * sc.w + sh.w, 0.f);
    ((float4*)g_h)[i] = h;
}

// ---------------- final: sigmoid(z2 @ W3^T + b3), warp per edge ----------------
__global__ void k_final(const float* __restrict__ W3, const float* __restrict__ b3,
                        float* __restrict__ out) {
    int w = (blockIdx.x * blockDim.x + threadIdx.x) >> 5;
    int lane = threadIdx.x & 31;
    if (w >= NE) return;
    const float4* zp = (const float4*)(g_z2 + (size_t)w * HID);
    const float4* wp = (const float4*)W3;
    float4 z0 = zp[lane], z1 = zp[lane + 32];
    float4 w0 = wp[lane], w1 = wp[lane + 32];
    float s = z0.x * w0.x + z0.y * w0.y + z0.z * w0.z + z0.w * w0.w
            + z1.x * w1.x + z1.y * w1.y + z1.z * w1.z + z1.w * w1.w;
#pragma unroll
    for (int off = 16; off > 0; off >>= 1) s += __shfl_xor_sync(0xffffffffu, s, off);
    if (lane == 0) {
        float v = s + b3[0];
        out[w] = 1.f / (1.f + expf(-v));
    }
}

// ---------------- launch ----------------
extern "C" void kernel_launch(void* const* d_in, const int* in_sizes, int n_in,
                              void* d_out, int out_size) {
    (void)in_sizes; (void)n_in; (void)out_size;
    const float* x     = (const float*)d_in[0];
    const int*   ei    = (const int*)d_in[1];
    const float* W_in  = (const float*)d_in[2];
    const float* Wrel  = (const float*)d_in[3];
    const float* brel  = (const float*)d_in[4];
    const float* Wroot = (const float*)d_in[5];
    const float* gamma = (const float*)d_in[6];
    const float* beta  = (const float*)d_in[7];
    const float* W1    = (const float*)d_in[8];
    const float* b1    = (const float*)d_in[9];
    const float* W2    = (const float*)d_in[10];
    const float* b2    = (const float*)d_in[11];
    const float* W3    = (const float*)d_in[12];
    const float* b3    = (const float*)d_in[13];
    float* out = (float*)d_out;
    const int* src = ei;
    const int* dst = ei + NE;

    // input fc
    k_input<<<NN, 256>>>(x, W_in);

    // CSR build (by dst)
    k_zero_cnt<<<(NN + 255) / 256, 256>>>();
    k_count<<<(NE + 255) / 256, 256>>>(dst);
    k_scan<<<1, 1024>>>();
    k_zero_cnt<<<(NN + 255) / 256, 256>>>();
    k_fill<<<(NE + 255) / 256, 256>>>(src, dst);

    dim3 gemm_n((NN + 127) / 128, 2);
    for (int l = 0; l < NLAYERS; l++) {
        k_agg<<<(NN * 32 + 255) / 256, 256>>>();
        k_gemm<0><<<gemm_n, 256>>>(Wrel + (size_t)l * HID * HID,
                                   Wroot + (size_t)l * HID * HID, HID,
                                   brel + (size_t)l * HID, 0, 0, NN);
        k_bnzero<<<1, 256>>>();
        k_bnstat<<<200, 256>>>();
        k_bnfin<<<1, 256>>>(gamma + (size_t)l * HID, beta + (size_t)l * HID);
        k_update<<<(NN * (HID / 4) + 255) / 256, 256>>>();
    }

    // edge MLP
    dim3 gemm_e((NE + 127) / 128, 2);
    k_gemm<1><<<gemm_e, 256>>>(W1, W1 + HID, 2 * HID, b1, src, dst, NE);
    k_gemm<2><<<gemm_e, 256>>>(W2, 0, HID, b2, 0, 0, NE);
    k_final<<<(NE * 32 + 255) / 256, 256>>>(W3, b3, out);
}

// round 2
// speedup vs baseline: 1.5399x; 1.5399x over previous
#include <cuda_runtime.h>
#include <math.h>

#define NN 50000
#define NE 500000
#define HID 256
#define NLAYERS 15
#define EPSV 1e-5f

// ---------------- scratch (device globals: allocation-free) ----------------
__device__ float g_h[(size_t)NN * HID];    // node features (residual stream)
__device__ float g_agg[(size_t)NN * HID];  // neighborhood sums
__device__ float g_out[(size_t)NN * HID];  // pre-BN layer output
__device__ float g_z1[(size_t)NE * HID];   // edge MLP hidden 1
__device__ float g_z2[(size_t)NE * HID];   // edge MLP hidden 2
__device__ int   g_rowptr[NN + 1];
__device__ int   g_cnt[NN];
__device__ int   g_col[NE];                // src node per CSR slot (sorted by dst)
__device__ float g_bnsum[HID];
__device__ float g_bnsq[HID];
__device__ float g_scale[HID];
__device__ float g_shift[HID];

// ---------------- input fc: h = x @ W_in^T  (IN_CH = 2) ----------------
__global__ void k_input(const float* __restrict__ x, const float* __restrict__ W_in) {
    int i = blockIdx.x;
    int c = threadIdx.x;
    if (i < NN) {
        float x0 = x[2 * i], x1 = x[2 * i + 1];
        g_h[(size_t)i * HID + c] = x0 * W_in[2 * c] + x1 * W_in[2 * c + 1];
    }
}

// ---------------- CSR build ----------------
__global__ void k_zero_cnt() {
    int i = blockIdx.x * blockDim.x + threadIdx.x;
    if (i < NN) g_cnt[i] = 0;
}

__global__ void k_count(const int* __restrict__ dst) {
    int i = blockIdx.x * blockDim.x + threadIdx.x;
    if (i < NE) atomicAdd(&g_cnt[dst[i]], 1);
}

// single-block exclusive scan over g_cnt -> g_rowptr
__global__ void k_scan() {
    __shared__ int s[1024];
    int t = threadIdx.x;
    const int CH = (NN + 1023) / 1024;  // 49
    int base = t * CH;
    int loc = 0;
    for (int j = 0; j < CH; j++) {
        int i = base + j;
        if (i < NN) loc += g_cnt[i];
    }
    s[t] = loc;
    __syncthreads();
    for (int off = 1; off < 1024; off <<= 1) {
        int v = 0;
        if (t >= off) v = s[t - off];
        __syncthreads();
        s[t] += v;
        __syncthreads();
    }
    int run = (t == 0) ? 0 : s[t - 1];
    for (int j = 0; j < CH; j++) {
        int i = base + j;
        if (i < NN) { g_rowptr[i] = run; run += g_cnt[i]; }
    }
    if (t == 0) g_rowptr[NN] = s[1023];
}

__global__ void k_fill(const int* __restrict__ src, const int* __restrict__ dst) {
    int i = blockIdx.x * blockDim.x + threadIdx.x;
    if (i < NE) {
        int d = dst[i];
        int p = atomicAdd(&g_cnt[d], 1);
        g_col[g_rowptr[d] + p] = src[i];
    }
}

// ---------------- aggregation: agg[i] = sum over in-edges of h[src] ----------------
__global__ void k_agg() {
    int w = (blockIdx.x * blockDim.x + threadIdx.x) >> 5;
    int lane = threadIdx.x & 31;
    if (w >= NN) return;
    int e0 = g_rowptr[w], e1 = g_rowptr[w + 1];
    float4 a0 = make_float4(0.f, 0.f, 0.f, 0.f);
    float4 a1 = make_float4(0.f, 0.f, 0.f, 0.f);
    for (int e = e0; e < e1; e++) {
        int s = g_col[e];
        const float4* hp = (const float4*)(g_h + (size_t)s * HID);
        float4 b0 = hp[lane];
        float4 b1 = hp[lane + 32];
        a0.x += b0.x; a0.y += b0.y; a0.z += b0.z; a0.w += b0.w;
        a1.x += b1.x; a1.y += b1.y; a1.z += b1.z; a1.w += b1.w;
    }
    float4* ap = (float4*)(g_agg + (size_t)w * HID);
    ap[lane] = a0;
    ap[lane + 32] = a1;
}

// ---------------- tf32 tensor-core dual-operand GEMM ----------------
// C[M, 256] = A1 @ B1^T (+ A2 @ B2^T) + bias, optional row-gather on A, optional relu.
// B rows are [N=256, K] row-major with row stride ldb. K per half = 256.
// MODE 0: A1=g_agg/B1=Wrel, A2=g_h/B2=Wroot, C=g_out, no relu
// MODE 1: A1=g_h gather src, A2=g_h gather dst (B=W1 halves, ldb=512), C=g_z1, relu
// MODE 2: A1=g_z1, single half (B=W2), C=g_z2, relu

__device__ __forceinline__ unsigned f2tf(float f) {
    unsigned r;
    asm("cvt.rna.tf32.f32 %0, %1;" : "=r"(r) : "f"(f));
    return r;
}

__device__ __forceinline__ void mma_tf32(float* c, const unsigned* a, const unsigned* b) {
    asm volatile(
        "mma.sync.aligned.m16n8k8.row.col.f32.tf32.tf32.f32 "
        "{%0,%1,%2,%3}, {%4,%5,%6,%7}, {%8,%9}, {%0,%1,%2,%3};"
        : "+f"(c[0]), "+f"(c[1]), "+f"(c[2]), "+f"(c[3])
        : "r"(a[0]), "r"(a[1]), "r"(a[2]), "r"(a[3]), "r"(b[0]), "r"(b[1]));
}

template <int MODE>
__global__ __launch_bounds__(256, 2) void k_gemm(
    const float* __restrict__ B1, const float* __restrict__ B2, int ldb,
    const float* __restrict__ bias, const int* __restrict__ idx1,
    const int* __restrict__ idx2, int M)
{
    constexpr int BK = 16;
    constexpr int LDS = 20;   // 16 + 4 pad: conflict-free frag loads
    constexpr bool RELU = (MODE != 0);
    constexpr bool GATHER = (MODE == 1);
    constexpr int NH = (MODE == 2) ? 1 : 2;

    const float* A1 = (MODE == 0) ? g_agg : ((MODE == 1) ? g_h : g_z1);
    const float* A2 = (MODE == 2) ? (const float*)0 : g_h;
    float* C = (MODE == 0) ? g_out : ((MODE == 1) ? g_z1 : g_z2);

    __shared__ unsigned As[128][LDS];
    __shared__ unsigned Bs[128][LDS];
    __shared__ int rix[128];

    int tid = threadIdx.x;
    int lane = tid & 31;
    int g = lane >> 2;        // 0..7
    int tg = lane & 3;        // 0..3
    int warp = tid >> 5;      // 0..7
    int wm = (warp & 1) * 64;
    int wn = (warp >> 1) * 32;
    int m0 = blockIdx.x * 128;
    int n0 = blockIdx.y * 128;

    float acc[4][4][4];
#pragma unroll
    for (int i = 0; i < 4; i++)
#pragma unroll
        for (int j = 0; j < 4; j++)
#pragma unroll
            for (int v = 0; v < 4; v++) acc[i][j][v] = 0.f;

    for (int hf = 0; hf < NH; hf++) {
        const float* A = hf ? A2 : A1;
        const float* B = hf ? B2 : B1;
        if (GATHER) {
            const int* idx = hf ? idx2 : idx1;
            __syncthreads();
            if (tid < 128) {
                int gm = m0 + tid;
                rix[tid] = (gm < M) ? idx[gm] : 0;
            }
            __syncthreads();
        }
        for (int kb = 0; kb < HID; kb += BK) {
            // stage A tile (128 x 16), convert to tf32
#pragma unroll
            for (int it = 0; it < 2; it++) {
                int t = tid + it * 256;       // 0..511 float4 slots
                int row = t >> 2;
                int kc = (t & 3) << 2;
                float4 v = make_float4(0.f, 0.f, 0.f, 0.f);
                if (GATHER) {
                    v = *(const float4*)(A + (size_t)rix[row] * HID + kb + kc);
                } else {
                    int gm = m0 + row;
                    if (gm < M) v = *(const float4*)(A + (size_t)gm * HID + kb + kc);
                }
                As[row][kc + 0] = f2tf(v.x);
                As[row][kc + 1] = f2tf(v.y);
                As[row][kc + 2] = f2tf(v.z);
                As[row][kc + 3] = f2tf(v.w);
            }
            // stage B tile (128 n-rows x 16 k)
#pragma unroll
            for (int it = 0; it < 2; it++) {
                int t = tid + it * 256;
                int row = t >> 2;
                int kc = (t & 3) << 2;
                float4 v = *(const float4*)(B + (size_t)(n0 + row) * ldb + kb + kc);
                Bs[row][kc + 0] = f2tf(v.x);
                Bs[row][kc + 1] = f2tf(v.y);
                Bs[row][kc + 2] = f2tf(v.z);
                Bs[row][kc + 3] = f2tf(v.w);
            }
            __syncthreads();
#pragma unroll
            for (int kk = 0; kk < BK; kk += 8) {
                unsigned afr[4][4];
#pragma unroll
                for (int mt = 0; mt < 4; mt++) {
                    int m = wm + mt * 16;
                    afr[mt][0] = As[m + g][kk + tg];
                    afr[mt][1] = As[m + g + 8][kk + tg];
                    afr[mt][2] = As[m + g][kk + tg + 4];
                    afr[mt][3] = As[m + g + 8][kk + tg + 4];
                }
                unsigned bfr[4][2];
#pragma unroll
                for (int nt = 0; nt < 4; nt++) {
                    int n = wn + nt * 8;
                    bfr[nt][0] = Bs[n + g][kk + tg];
                    bfr[nt][1] = Bs[n + g][kk + tg + 4];
                }
#pragma unroll
                for (int mt = 0; mt < 4; mt++)
#pragma unroll
                    for (int nt = 0; nt < 4; nt++)
                        mma_tf32(acc[mt][nt], afr[mt], bfr[nt]);
            }
            __syncthreads();
        }
    }

    // epilogue: bias (+relu), store
#pragma unroll
    for (int mt = 0; mt < 4; mt++) {
        int r0 = m0 + wm + mt * 16 + g;
#pragma unroll
        for (int nt = 0; nt < 4; nt++) {
            int col = n0 + wn + nt * 8 + tg * 2;
            float b0 = bias[col], b1 = bias[col + 1];
            float c0 = acc[mt][nt][0] + b0;
            float c1 = acc[mt][nt][1] + b1;
            float c2 = acc[mt][nt][2] + b0;
            float c3 = acc[mt][nt][3] + b1;
            if (RELU) {
                c0 = fmaxf(c0, 0.f); c1 = fmaxf(c1, 0.f);
                c2 = fmaxf(c2, 0.f); c3 = fmaxf(c3, 0.f);
            }
            if (r0 < M)
                *(float2*)(C + (size_t)r0 * HID + col) = make_float2(c0, c1);
            if (r0 + 8 < M)
                *(float2*)(C + (size_t)(r0 + 8) * HID + col) = make_float2(c2, c3);
        }
    }
}

// ---------------- batchnorm ----------------
__global__ void k_bnzero() {
    int c = threadIdx.x;
    g_bnsum[c] = 0.f;
    g_bnsq[c] = 0.f;
}

__global__ void k_bnstat() {
    int c = threadIdx.x;           // channel
    int r0 = blockIdx.x * 250;     // 200 blocks x 250 rows = 50000
    float s = 0.f, q = 0.f;
    for (int r = 0; r < 250; r++) {
        float v = g_out[(size_t)(r0 + r) * HID + c];
        s += v;
        q += v * v;
    }
    atomicAdd(&g_bnsum[c], s);
    atomicAdd(&g_bnsq[c], q);
}

__global__ void k_bnfin(const float* __restrict__ gamma, const float* __restrict__ beta) {
    int c = threadIdx.x;
    float mean = g_bnsum[c] * (1.f / NN);
    float var = g_bnsq[c] * (1.f / NN) - mean * mean;
    float inv = rsqrtf(var + EPSV);
    float sc = gamma[c] * inv;
    g_scale[c] = sc;
    g_shift[c] = beta[c] - mean * sc;
}

// h += relu(out * scale + shift)
__global__ void k_update() {
    int i = blockIdx.x * blockDim.x + threadIdx.x;  // over NN*64 float4s
    if (i >= NN * (HID / 4)) return;
    int c4 = (i & (HID / 4 - 1)) * 4;
    float4 o = ((const float4*)g_out)[i];
    float4 sc = *(const float4*)(g_scale + c4);
    float4 sh = *(const float4*)(g_shift + c4);
    float4 h = ((const float4*)g_h)[i];
    h.x += fmaxf(o.x * sc.x + sh.x, 0.f);
    h.y += fmaxf(o.y * sc.y + sh.y, 0.f);
    h.z += fmaxf(o.z * sc.z + sh.z, 0.f);
    h.w += fmaxf(o.w * sc.w + sh.w, 0.f);
    ((float4*)g_h)[i] = h;
}

// ---------------- final: sigmoid(z2 @ W3^T + b3), warp per edge ----------------
__global__ void k_final(const float* __restrict__ W3, const float* __restrict__ b3,
                        float* __restrict__ out) {
    int w = (blockIdx.x * blockDim.x + threadIdx.x) >> 5;
    int lane = threadIdx.x & 31;
    if (w >= NE) return;
    const float4* zp = (const float4*)(g_z2 + (size_t)w * HID);
    const float4* wp = (const float4*)W3;
    float4 z0 = zp[lane], z1 = zp[lane + 32];
    float4 w0 = wp[lane], w1 = wp[lane + 32];
    float s = z0.x * w0.x + z0.y * w0.y + z0.z * w0.z + z0.w * w0.w
            + z1.x * w1.x + z1.y * w1.y + z1.z * w1.z + z1.w * w1.w;
#pragma unroll
    for (int off = 16; off > 0; off >>= 1) s += __shfl_xor_sync(0xffffffffu, s, off);
    if (lane == 0) {
        float v = s + b3[0];
        out[w] = 1.f / (1.f + expf(-v));
    }
}

// ---------------- launch ----------------
extern "C" void kernel_launch(void* const* d_in, const int* in_sizes, int n_in,
                              void* d_out, int out_size) {
    (void)in_sizes; (void)n_in; (void)out_size;
    const float* x     = (const float*)d_in[0];
    const int*   ei    = (const int*)d_in[1];
    const float* W_in  = (const float*)d_in[2];
    const float* Wrel  = (const float*)d_in[3];
    const float* brel  = (const float*)d_in[4];
    const float* Wroot = (const float*)d_in[5];
    const float* gamma = (const float*)d_in[6];
    const float* beta  = (const float*)d_in[7];
    const float* W1    = (const float*)d_in[8];
    const float* b1    = (const float*)d_in[9];
    const float* W2    = (const float*)d_in[10];
    const float* b2    = (const float*)d_in[11];
    const float* W3    = (const float*)d_in[12];
    const float* b3    = (const float*)d_in[13];
    float* out = (float*)d_out;
    const int* src = ei;
    const int* dst = ei + NE;

    // input fc
    k_input<<<NN, 256>>>(x, W_in);

    // CSR build (by dst)
    k_zero_cnt<<<(NN + 255) / 256, 256>>>();
    k_count<<<(NE + 255) / 256, 256>>>(dst);
    k_scan<<<1, 1024>>>();
    k_zero_cnt<<<(NN + 255) / 256, 256>>>();
    k_fill<<<(NE + 255) / 256, 256>>>(src, dst);

    dim3 gemm_n((NN + 127) / 128, 2);
    for (int l = 0; l < NLAYERS; l++) {
        k_agg<<<(NN * 32 + 255) / 256, 256>>>();
        k_gemm<0><<<gemm_n, 256>>>(Wrel + (size_t)l * HID * HID,
                                   Wroot + (size_t)l * HID * HID, HID,
                                   brel + (size_t)l * HID, 0, 0, NN);
        k_bnzero<<<1, 256>>>();
        k_bnstat<<<200, 256>>>();
        k_bnfin<<<1, 256>>>(gamma + (size_t)l * HID, beta + (size_t)l * HID);
        k_update<<<(NN * (HID / 4) + 255) / 256, 256>>>();
    }

    // edge MLP
    dim3 gemm_e((NE + 127) / 128, 2);
    k_gemm<1><<<gemm_e, 256>>>(W1, W1 + HID, 2 * HID, b1, src, dst, NE);
    k_gemm<2><<<gemm_e, 256>>>(W2, 0, HID, b2, 0, 0, NE);
    k_final<<<(NE * 32 + 255) / 256, 256>>>(W3, b3, out);
}

// round 3
// speedup vs baseline: 2.8187x; 1.8305x over previous
#include <cuda_runtime.h>
#include <math.h>

#define NN 50000
#define NE 500000
#define HID 256
#define NLAYERS 15
#define EPSV 1e-5f

// ---------------- scratch (device globals: allocation-free) ----------------
__device__ float g_h[(size_t)NN * HID];    // node features (residual stream)
__device__ float g_agg[(size_t)NN * HID];  // neighborhood sums
__device__ float g_out[(size_t)NN * HID];  // pre-BN layer output
__device__ float g_u[(size_t)NN * HID];    // h @ W1a^T + b1 (edge MLP precompute)
__device__ float g_v[(size_t)NN * HID];    // h @ W1b^T
__device__ int   g_rowptr[NN + 1];
__device__ int   g_cnt[NN];
__device__ int   g_col[NE];                // src node per CSR slot (sorted by dst)
__device__ float g_bnsum[HID];
__device__ float g_bnsq[HID];
__device__ float g_scale[HID];
__device__ float g_shift[HID];
__device__ float g_zb[HID];                // zero bias (never written)

// ---------------- input fc: h = x @ W_in^T  (IN_CH = 2); fused zeroing ----------------
__global__ void k_input(const float* __restrict__ x, const float* __restrict__ W_in) {
    int i = blockIdx.x;
    int c = threadIdx.x;
    if (c == 0) g_cnt[i] = 0;
    if (i == 0) { g_bnsum[c] = 0.f; g_bnsq[c] = 0.f; }
    float x0 = x[2 * i], x1 = x[2 * i + 1];
    g_h[(size_t)i * HID + c] = x0 * W_in[2 * c] + x1 * W_in[2 * c + 1];
}

// ---------------- CSR build ----------------
__global__ void k_count(const int* __restrict__ dst) {
    int i = blockIdx.x * blockDim.x + threadIdx.x;
    if (i < NE) atomicAdd(&g_cnt[dst[i]], 1);
}

// single-block exclusive scan over g_cnt -> g_rowptr (warp-shuffle based), re-zeros g_cnt
__global__ void k_scan() {
    __shared__ int ws[32];
    int t = threadIdx.x;
    int lane = t & 31, wid = t >> 5;
    const int CH = (NN + 1023) / 1024;  // 49
    int base = t * CH;
    int loc = 0;
#pragma unroll 1
    for (int j = 0; j < CH; j++) {
        int i = base + j;
        if (i < NN) loc += g_cnt[i];
    }
    // warp inclusive scan
    int v = loc;
#pragma unroll
    for (int off = 1; off < 32; off <<= 1) {
        int n = __shfl_up_sync(0xffffffffu, v, off);
        if (lane >= off) v += n;
    }
    if (lane == 31) ws[wid] = v;
    __syncthreads();
    if (wid == 0) {
        int w = ws[lane];
#pragma unroll
        for (int off = 1; off < 32; off <<= 1) {
            int n = __shfl_up_sync(0xffffffffu, w, off);
            if (lane >= off) w += n;
        }
        ws[lane] = w;
    }
    __syncthreads();
    int run = (v - loc) + (wid ? ws[wid - 1] : 0);
#pragma unroll 1
    for (int j = 0; j < CH; j++) {
        int i = base + j;
        if (i < NN) { g_rowptr[i] = run; run += g_cnt[i]; g_cnt[i] = 0; }
    }
    if (t == 1023) g_rowptr[NN] = ws[31];
}

__global__ void k_fill(const int* __restrict__ src, const int* __restrict__ dst) {
    int i = blockIdx.x * blockDim.x + threadIdx.x;
    if (i < NE) {
        int d = dst[i];
        int p = atomicAdd(&g_cnt[d], 1);
        g_col[g_rowptr[d] + p] = src[i];
    }
}

// ---------------- aggregation: agg[i] = sum over in-edges of h[src] ----------------
__global__ void k_agg() {
    int w = (blockIdx.x * blockDim.x + threadIdx.x) >> 5;
    int lane = threadIdx.x & 31;
    if (w >= NN) return;
    int e0 = g_rowptr[w], e1 = g_rowptr[w + 1];
    float4 a0 = make_float4(0.f, 0.f, 0.f, 0.f);
    float4 a1 = make_float4(0.f, 0.f, 0.f, 0.f);
    for (int e = e0; e < e1; e++) {
        int s = g_col[e];
        const float4* hp = (const float4*)(g_h + (size_t)s * HID);
        float4 b0 = hp[lane];
        float4 b1 = hp[lane + 32];
        a0.x += b0.x; a0.y += b0.y; a0.z += b0.z; a0.w += b0.w;
        a1.x += b1.x; a1.y += b1.y; a1.z += b1.z; a1.w += b1.w;
    }
    float4* ap = (float4*)(g_agg + (size_t)w * HID);
    ap[lane] = a0;
    ap[lane + 32] = a1;
}

// ---------------- tf32 mma helpers ----------------
__device__ __forceinline__ unsigned f2tf(float f) {
    unsigned r;
    asm("cvt.rna.tf32.f32 %0, %1;" : "=r"(r) : "f"(f));
    return r;
}

__device__ __forceinline__ void mma_tf32(float* c, const unsigned* a, const unsigned* b) {
    asm volatile(
        "mma.sync.aligned.m16n8k8.row.col.f32.tf32.tf32.f32 "
        "{%0,%1,%2,%3}, {%4,%5,%6,%7}, {%8,%9}, {%0,%1,%2,%3};"
        : "+f"(c[0]), "+f"(c[1]), "+f"(c[2]), "+f"(c[3])
        : "r"(a[0]), "r"(a[1]), "r"(a[2]), "r"(a[3]), "r"(b[0]), "r"(b[1]));
}

// ---------------- tf32 tensor-core GEMM (software-pipelined LDG) ----------------
// C[M, 256] = A1 @ B1^T (+ A2 @ B2^T) + bias.  B rows [256, K] row-major stride ldb.
// MODE 0: A1=g_agg/B1=Wrel, A2=g_h/B2=Wroot, C=g_out  (dual, K=2x256)
// MODE 1: A1=g_h/B1=W1a (ldb 512), C=g_u
// MODE 2: A1=g_h/B1=W1b (ldb 512), C=g_v
template <int MODE>
__device__ __forceinline__ void ld_tiles(int kbi, int m0, int n0, int tid, int M,
                                         const float* __restrict__ B1,
                                         const float* __restrict__ B2, int ldb,
                                         float4& a0, float4& a1, float4& b0, float4& b1v) {
    int hf = kbi >> 4;
    int kb = (kbi & 15) * 16;
    const float* A = (MODE == 0 && hf == 1) ? g_h : ((MODE == 0) ? g_agg : g_h);
    const float* B = hf ? B2 : B1;
    {
        int t = tid, row = t >> 2, kc = (t & 3) << 2;
        int gm = m0 + row;
        a0 = (gm < M) ? *(const float4*)(A + (size_t)gm * HID + kb + kc)
                      : make_float4(0.f, 0.f, 0.f, 0.f);
        b0 = *(const float4*)(B + (size_t)(n0 + row) * ldb + kb + kc);
    }
    {
        int t = tid + 256, row = t >> 2, kc = (t & 3) << 2;
        int gm = m0 + row;
        a1 = (gm < M) ? *(const float4*)(A + (size_t)gm * HID + kb + kc)
                      : make_float4(0.f, 0.f, 0.f, 0.f);
        b1v = *(const float4*)(B + (size_t)(n0 + row) * ldb + kb + kc);
    }
}

template <int MODE>
__global__ __launch_bounds__(256, 2) void k_gemm(
    const float* __restrict__ B1, const float* __restrict__ B2, int ldb,
    const float* __restrict__ bias, int M)
{
    constexpr int LDS = 20;
    constexpr int NKB = (MODE == 0) ? 32 : 16;

    float* C = (MODE == 0) ? g_out : ((MODE == 1) ? g_u : g_v);

    __shared__ unsigned As[128][LDS];
    __shared__ unsigned Bs[128][LDS];

    int tid = threadIdx.x;
    int lane = tid & 31;
    int g = lane >> 2;
    int tg = lane & 3;
    int warp = tid >> 5;
    int wm = (warp & 1) * 64;
    int wn = (warp >> 1) * 32;
    int m0 = blockIdx.x * 128;
    int n0 = blockIdx.y * 128;

    float acc[4][4][4];
#pragma unroll
    for (int i = 0; i < 4; i++)
#pragma unroll
        for (int j = 0; j < 4; j++)
#pragma unroll
            for (int v = 0; v < 4; v++) acc[i][j][v] = 0.f;

    float4 a0, a1, b0, b1v;
    ld_tiles<MODE>(0, m0, n0, tid, M, B1, B2, ldb, a0, a1, b0, b1v);

    int r0s = tid >> 2, kc0 = (tid & 3) << 2;
    int r1s = (tid + 256) >> 2;

    for (int kbi = 0; kbi < NKB; kbi++) {
        // commit staged regs to smem (tf32 convert)
        As[r0s][kc0 + 0] = f2tf(a0.x); As[r0s][kc0 + 1] = f2tf(a0.y);
        As[r0s][kc0 + 2] = f2tf(a0.z); As[r0s][kc0 + 3] = f2tf(a0.w);
        As[r1s][kc0 + 0] = f2tf(a1.x); As[r1s][kc0 + 1] = f2tf(a1.y);
        As[r1s][kc0 + 2] = f2tf(a1.z); As[r1s][kc0 + 3] = f2tf(a1.w);
        Bs[r0s][kc0 + 0] = f2tf(b0.x); Bs[r0s][kc0 + 1] = f2tf(b0.y);
        Bs[r0s][kc0 + 2] = f2tf(b0.z); Bs[r0s][kc0 + 3] = f2tf(b0.w);
        Bs[r1s][kc0 + 0] = f2tf(b1v.x); Bs[r1s][kc0 + 1] = f2tf(b1v.y);
        Bs[r1s][kc0 + 2] = f2tf(b1v.z); Bs[r1s][kc0 + 3] = f2tf(b1v.w);
        __syncthreads();
        // prefetch next tile while computing
        if (kbi + 1 < NKB)
            ld_tiles<MODE>(kbi + 1, m0, n0, tid, M, B1, B2, ldb, a0, a1, b0, b1v);
#pragma unroll
        for (int kk = 0; kk < 16; kk += 8) {
            unsigned afr[4][4];
#pragma unroll
            for (int mt = 0; mt < 4; mt++) {
                int m = wm + mt * 16;
                afr[mt][0] = As[m + g][kk + tg];
                afr[mt][1] = As[m + g + 8][kk + tg];
                afr[mt][2] = As[m + g][kk + tg + 4];
                afr[mt][3] = As[m + g + 8][kk + tg + 4];
            }
            unsigned bfr[4][2];
#pragma unroll
            for (int nt = 0; nt < 4; nt++) {
                int n = wn + nt * 8;
                bfr[nt][0] = Bs[n + g][kk + tg];
                bfr[nt][1] = Bs[n + g][kk + tg + 4];
            }
#pragma unroll
            for (int mt = 0; mt < 4; mt++)
#pragma unroll
                for (int nt = 0; nt < 4; nt++)
                    mma_tf32(acc[mt][nt], afr[mt], bfr[nt]);
        }
        __syncthreads();
    }

    // epilogue: bias, store
#pragma unroll
    for (int mt = 0; mt < 4; mt++) {
        int r0 = m0 + wm + mt * 16 + g;
#pragma unroll
        for (int nt = 0; nt < 4; nt++) {
            int col = n0 + wn + nt * 8 + tg * 2;
            float bb0 = bias[col], bb1 = bias[col + 1];
            if (r0 < M)
                *(float2*)(C + (size_t)r0 * HID + col) =
                    make_float2(acc[mt][nt][0] + bb0, acc[mt][nt][1] + bb1);
            if (r0 + 8 < M)
                *(float2*)(C + (size_t)(r0 + 8) * HID + col) =
                    make_float2(acc[mt][nt][2] + bb0, acc[mt][nt][3] + bb1);
        }
    }
}

// ---------------- fused edge kernel ----------------
// per 64 edges: z1 = relu(u[src]+v[dst]) on the fly -> z2 = relu(z1@W2^T+b2) in regs
// -> logit = z2 . W3 + b3 -> sigmoid -> out.  Never materializes z1/z2.
__global__ __launch_bounds__(256, 2) void k_edge(
    const float* __restrict__ W2, const float* __restrict__ b2,
    const float* __restrict__ W3, const float* __restrict__ b3,
    const int* __restrict__ src, const int* __restrict__ dst,
    float* __restrict__ out)
{
    constexpr int LDS = 20;
    __shared__ unsigned As[64][LDS];    // z1 tile (64 edges x 16 k)
    __shared__ unsigned Bs[256][LDS];   // W2 tile (256 n x 16 k)
    __shared__ int rs[64], rd[64];
    __shared__ float lg[64];

    int tid = threadIdx.x;
    int lane = tid & 31;
    int g = lane >> 2;
    int tg = lane & 3;
    int warp = tid >> 5;
    int wm = (warp & 1) * 32;
    int wn = (warp >> 1) * 64;
    int m0 = blockIdx.x * 64;

    if (tid < 64) {
        int e = m0 + tid;
        rs[tid] = (e < NE) ? src[e] : 0;
    } else if (tid < 128) {
        int e = m0 + tid - 64;
        rd[tid - 64] = (e < NE) ? dst[e] : 0;
    }
    if (tid < 64) lg[tid] = 0.f;
    __syncthreads();

    float acc[2][8][4];
#pragma unroll
    for (int i = 0; i < 2; i++)
#pragma unroll
        for (int j = 0; j < 8; j++)
#pragma unroll
            for (int v = 0; v < 4; v++) acc[i][j][v] = 0.f;

    int arow = tid >> 2, akc = (tid & 3) << 2;

    // prefetch K-block 0
    float4 av, bv[4];
    {
        const float* up = g_u + (size_t)rs[arow] * HID + akc;
        const float* vp = g_v + (size_t)rd[arow] * HID + akc;
        float4 uu = *(const float4*)up;
        float4 vv = *(const float4*)vp;
        av = make_float4(fmaxf(uu.x + vv.x, 0.f), fmaxf(uu.y + vv.y, 0.f),
                         fmaxf(uu.z + vv.z, 0.f), fmaxf(uu.w + vv.w, 0.f));
#pragma unroll
        for (int it = 0; it < 4; it++) {
            int t = tid + it * 256, row = t >> 2, kc = (t & 3) << 2;
            bv[it] = *(const float4*)(W2 + (size_t)row * HID + kc);
        }
    }

    for (int kbi = 0; kbi < 16; kbi++) {
        As[arow][akc + 0] = f2tf(av.x); As[arow][akc + 1] = f2tf(av.y);
        As[arow][akc + 2] = f2tf(av.z); As[arow][akc + 3] = f2tf(av.w);
#pragma unroll
        for (int it = 0; it < 4; it++) {
            int t = tid + it * 256, row = t >> 2, kc = (t & 3) << 2;
            Bs[row][kc + 0] = f2tf(bv[it].x); Bs[row][kc + 1] = f2tf(bv[it].y);
            Bs[row][kc + 2] = f2tf(bv[it].z); Bs[row][kc + 3] = f2tf(bv[it].w);
        }
        __syncthreads();
        if (kbi + 1 < 16) {
            int kb = (kbi + 1) * 16;
            float4 uu = *(const float4*)(g_u + (size_t)rs[arow] * HID + kb + akc);
            float4 vv = *(const float4*)(g_v + (size_t)rd[arow] * HID + kb + akc);
            av = make_float4(fmaxf(uu.x + vv.x, 0.f), fmaxf(uu.y + vv.y, 0.f),
                             fmaxf(uu.z + vv.z, 0.f), fmaxf(uu.w + vv.w, 0.f));
#pragma unroll
            for (int it = 0; it < 4; it++) {
                int t = tid + it * 256, row = t >> 2, kc = (t & 3) << 2;
                bv[it] = *(const float4*)(W2 + (size_t)row * HID + kb + kc);
            }
        }
#pragma unroll
        for (int kk = 0; kk < 16; kk += 8) {
            unsigned afr[2][4];
#pragma unroll
            for (int mt = 0; mt < 2; mt++) {
                int m = wm + mt * 16;
                afr[mt][0] = As[m + g][kk + tg];
                afr[mt][1] = As[m + g + 8][kk + tg];
                afr[mt][2] = As[m + g][kk + tg + 4];
                afr[mt][3] = As[m + g + 8][kk + tg + 4];
            }
            unsigned bfr[8][2];
#pragma unroll
            for (int nt = 0; nt < 8; nt++) {
                int n = wn + nt * 8;
                bfr[nt][0] = Bs[n + g][kk + tg];
                bfr[nt][1] = Bs[n + g][kk + tg + 4];
            }
#pragma unroll
            for (int mt = 0; mt < 2; mt++)
#pragma unroll
                for (int nt = 0; nt < 8; nt++)
                    mma_tf32(acc[mt][nt], afr[mt], bfr[nt]);
        }
        __syncthreads();
    }

    // epilogue: z2 = relu(acc + b2), partial dot with W3, reduce
#pragma unroll
    for (int mt = 0; mt < 2; mt++) {
        int rl = wm + mt * 16 + g;
        float p0 = 0.f, p1 = 0.f;
#pragma unroll
        for (int nt = 0; nt < 8; nt++) {
            int col = wn + nt * 8 + tg * 2;
            float w3a = W3[col], w3b = W3[col + 1];
            float b2a = b2[col], b2b = b2[col + 1];
            p0 += fmaxf(acc[mt][nt][0] + b2a, 0.f) * w3a
                + fmaxf(acc[mt][nt][1] + b2b, 0.f) * w3b;
            p1 += fmaxf(acc[mt][nt][2] + b2a, 0.f) * w3a
                + fmaxf(acc[mt][nt][3] + b2b, 0.f) * w3b;
        }
        p0 += __shfl_xor_sync(0xffffffffu, p0, 1);
        p0 += __shfl_xor_sync(0xffffffffu, p0, 2);
        p1 += __shfl_xor_sync(0xffffffffu, p1, 1);
        p1 += __shfl_xor_sync(0xffffffffu, p1, 2);
        if (tg == 0) {
            atomicAdd(&lg[rl], p0);
            atomicAdd(&lg[rl + 8], p1);
        }
    }
    __syncthreads();
    if (tid < 64) {
        int e = m0 + tid;
        if (e < NE) out[e] = 1.f / (1.f + expf(-(lg[tid] + b3[0])));
    }
}

// ---------------- batchnorm ----------------
__global__ void k_bnstat() {
    int c = threadIdx.x;           // channel
    int r0 = blockIdx.x * 250;     // 200 blocks x 250 rows = 50000
    float s = 0.f, q = 0.f;
    for (int r = 0; r < 250; r++) {
        float v = g_out[(size_t)(r0 + r) * HID + c];
        s += v;
        q += v * v;
    }
    atomicAdd(&g_bnsum[c], s);
    atomicAdd(&g_bnsq[c], q);
}

__global__ void k_bnfin(const float* __restrict__ gamma, const float* __restrict__ beta) {
    int c = threadIdx.x;
    float mean = g_bnsum[c] * (1.f / NN);
    float var = g_bnsq[c] * (1.f / NN) - mean * mean;
    float inv = rsqrtf(var + EPSV);
    float sc = gamma[c] * inv;
    g_scale[c] = sc;
    g_shift[c] = beta[c] - mean * sc;
}

// h += relu(out * scale + shift); block 0 re-zeros BN accumulators for next layer
__global__ void k_update() {
    int i = blockIdx.x * blockDim.x + threadIdx.x;  // over NN*64 float4s
    if (blockIdx.x == 0) { g_bnsum[threadIdx.x] = 0.f; g_bnsq[threadIdx.x] = 0.f; }
    if (i >= NN * (HID / 4)) return;
    int c4 = (i & (HID / 4 - 1)) * 4;
    float4 o = ((const float4*)g_out)[i];
    float4 sc = *(const float4*)(g_scale + c4);
    float4 sh = *(const float4*)(g_shift + c4);
    float4 h = ((const float4*)g_h)[i];
    h.x += fmaxf(o.x * sc.x + sh.x, 0.f);
    h.y += fmaxf(o.y * sc.y + sh.y, 0.f);
    h.z += fmaxf(o.z * sc.z + sh.z, 0.f);
    h.w += fmaxf(o.w * sc.w + sh.w, 0.f);
    ((float4*)g_h)[i] = h;
}

// ---------------- launch ----------------
extern "C" void kernel_launch(void* const* d_in, const int* in_sizes, int n_in,
                              void* d_out, int out_size) {
    (void)in_sizes; (void)n_in; (void)out_size;
    const float* x     = (const float*)d_in[0];
    const int*   ei    = (const int*)d_in[1];
    const float* W_in  = (const float*)d_in[2];
    const float* Wrel  = (const float*)d_in[3];
    const float* brel  = (const float*)d_in[4];
    const float* Wroot = (const float*)d_in[5];
    const float* gamma = (const float*)d_in[6];
    const float* beta  = (const float*)d_in[7];
    const float* W1    = (const float*)d_in[8];
    const float* b1    = (const float*)d_in[9];
    const float* W2    = (const float*)d_in[10];
    const float* b2    = (const float*)d_in[11];
    const float* W3    = (const float*)d_in[12];
    const float* b3    = (const float*)d_in[13];
    float* out = (float*)d_out;
    const int* src = ei;
    const int* dst = ei + NE;

    // input fc (+ zero cnt/bn accumulators)
    k_input<<<NN, 256>>>(x, W_in);

    // CSR build (by dst): count -> scan(+rezero) -> fill
    k_count<<<(NE + 255) / 256, 256>>>(dst);
    k_scan<<<1, 1024>>>();
    k_fill<<<(NE + 255) / 256, 256>>>(src, dst);

    dim3 gemm_n((NN + 127) / 128, 2);
    for (int l = 0; l < NLAYERS; l++) {
        k_agg<<<(NN * 32 + 255) / 256, 256>>>();
        k_gemm<0><<<gemm_n, 256>>>(Wrel + (size_t)l * HID * HID,
                                   Wroot + (size_t)l * HID * HID, HID,
                                   brel + (size_t)l * HID, NN);
        k_bnstat<<<200, 256>>>();
        k_bnfin<<<1, 256>>>(gamma + (size_t)l * HID, beta + (size_t)l * HID);
        k_update<<<(NN * (HID / 4) + 255) / 256, 256>>>();
    }

    // edge MLP: u = h@W1a^T + b1, v = h@W1b^T, then fused edge kernel
    k_gemm<1><<<gemm_n, 256>>>(W1, (const float*)0, 2 * HID, b1, NN);
    k_gemm<2><<<gemm_n, 256>>>(W1 + HID, (const float*)0, 2 * HID, g_zb, NN);
    k_edge<<<(NE + 63) / 64, 256>>>(W2, b2, W3, b3, src, dst, out);
}

// round 4
// speedup vs baseline: 3.0263x; 1.0737x over previous
#include <cuda_runtime.h>
#include <cuda_bf16.h>
#include <math.h>

#define NN 50000
#define NE 500000
#define HID 256
#define NLAYERS 15
#define EPSV 1e-5f

// ---------------- scratch (device globals: allocation-free) ----------------
__device__ float g_h[(size_t)NN * HID];            // node features fp32 (GEMM operand)
__device__ __nv_bfloat16 g_hb[(size_t)NN * HID];   // bf16 copy (gather path)
__device__ float g_agg[(size_t)NN * HID];          // neighborhood sums
__device__ float g_out[(size_t)NN * HID];          // pre-BN layer output
__device__ __nv_bfloat16 g_u[(size_t)NN * HID];    // h @ W1a^T + b1 (bf16)
__device__ __nv_bfloat16 g_v[(size_t)NN * HID];    // h @ W1b^T (bf16)
__device__ int   g_rowptr[NN + 1];
__device__ int   g_cnt[NN];
__device__ int   g_col[NE];
__device__ float g_bnsum[HID];
__device__ float g_bnsq[HID];
__device__ float g_scale[HID];
__device__ float g_shift[HID];
__device__ float g_zb[HID];                        // zero bias (never written)

__device__ __forceinline__ float2 bf2f(unsigned u) {
    __nv_bfloat162 b = *(__nv_bfloat162*)&u;
    return make_float2(__bfloat162float(b.x), __bfloat162float(b.y));
}
__device__ __forceinline__ unsigned f2bf2(float a, float b) {
    __nv_bfloat162 p = __floats2bfloat162_rn(a, b);
    return *(unsigned*)&p;
}

// ---------------- input fc ----------------
__global__ void k_input(const float* __restrict__ x, const float* __restrict__ W_in) {
    int i = blockIdx.x;
    int c = threadIdx.x;
    if (c == 0) g_cnt[i] = 0;
    float x0 = x[2 * i], x1 = x[2 * i + 1];
    float v = x0 * W_in[2 * c] + x1 * W_in[2 * c + 1];
    g_h[(size_t)i * HID + c] = v;
    g_hb[(size_t)i * HID + c] = __float2bfloat16(v);
}

// ---------------- CSR build ----------------
__global__ void k_count(const int* __restrict__ dst) {
    int i = blockIdx.x * blockDim.x + threadIdx.x;
    if (i < NE) atomicAdd(&g_cnt[dst[i]], 1);
}

__global__ void k_scan() {
    __shared__ int ws[32];
    int t = threadIdx.x;
    int lane = t & 31, wid = t >> 5;
    const int CH = (NN + 1023) / 1024;
    int base = t * CH;
    int loc = 0;
#pragma unroll 1
    for (int j = 0; j < CH; j++) {
        int i = base + j;
        if (i < NN) loc += g_cnt[i];
    }
    int v = loc;
#pragma unroll
    for (int off = 1; off < 32; off <<= 1) {
        int n = __shfl_up_sync(0xffffffffu, v, off);
        if (lane >= off) v += n;
    }
    if (lane == 31) ws[wid] = v;
    __syncthreads();
    if (wid == 0) {
        int w = ws[lane];
#pragma unroll
        for (int off = 1; off < 32; off <<= 1) {
            int n = __shfl_up_sync(0xffffffffu, w, off);
            if (lane >= off) w += n;
        }
        ws[lane] = w;
    }
    __syncthreads();
    int run = (v - loc) + (wid ? ws[wid - 1] : 0);
#pragma unroll 1
    for (int j = 0; j < CH; j++) {
        int i = base + j;
        if (i < NN) { g_rowptr[i] = run; run += g_cnt[i]; g_cnt[i] = 0; }
    }
    if (t == 1023) g_rowptr[NN] = ws[31];
}

__global__ void k_fill(const int* __restrict__ src, const int* __restrict__ dst) {
    int i = blockIdx.x * blockDim.x + threadIdx.x;
    if (i < NE) {
        int d = dst[i];
        int p = atomicAdd(&g_cnt[d], 1);
        g_col[g_rowptr[d] + p] = src[i];
    }
}

// ---------------- aggregation (bf16 gather, fp32 accumulate) ----------------
// warp per node, 8 channels per lane; block 0 zeroes BN accumulators for the
// upcoming gemm<0> stat accumulation.
__global__ void k_agg() {
    if (blockIdx.x == 0 && threadIdx.x < HID) {
        g_bnsum[threadIdx.x] = 0.f;
        g_bnsq[threadIdx.x] = 0.f;
    }
    int w = (blockIdx.x * blockDim.x + threadIdx.x) >> 5;
    int lane = threadIdx.x & 31;
    if (w >= NN) return;
    int e0 = g_rowptr[w], e1 = g_rowptr[w + 1];
    float a[8];
#pragma unroll
    for (int i = 0; i < 8; i++) a[i] = 0.f;
    for (int e = e0; e < e1; e++) {
        int s = g_col[e];
        uint4 r = *(const uint4*)(g_hb + (size_t)s * HID + lane * 8);
        float2 f0 = bf2f(r.x), f1 = bf2f(r.y), f2 = bf2f(r.z), f3 = bf2f(r.w);
        a[0] += f0.x; a[1] += f0.y; a[2] += f1.x; a[3] += f1.y;
        a[4] += f2.x; a[5] += f2.y; a[6] += f3.x; a[7] += f3.y;
    }
    float4* ap = (float4*)(g_agg + (size_t)w * HID + lane * 8);
    ap[0] = make_float4(a[0], a[1], a[2], a[3]);
    ap[1] = make_float4(a[4], a[5], a[6], a[7]);
}

// ---------------- tf32 mma helpers ----------------
__device__ __forceinline__ unsigned f2tf(float f) {
    unsigned r;
    asm("cvt.rna.tf32.f32 %0, %1;" : "=r"(r) : "f"(f));
    return r;
}

__device__ __forceinline__ void mma_tf32(float* c, const unsigned* a, const unsigned* b) {
    asm volatile(
        "mma.sync.aligned.m16n8k8.row.col.f32.tf32.tf32.f32 "
        "{%0,%1,%2,%3}, {%4,%5,%6,%7}, {%8,%9}, {%0,%1,%2,%3};"
        : "+f"(c[0]), "+f"(c[1]), "+f"(c[2]), "+f"(c[3])
        : "r"(a[0]), "r"(a[1]), "r"(a[2]), "r"(a[3]), "r"(b[0]), "r"(b[1]));
}

// ---------------- tf32 tensor-core GEMM (double-buffered smem) ----------------
// MODE 0: g_out = g_agg@Wrel^T + g_h@Wroot^T + brel ; fused BN stats (fp32 out)
// MODE 1: g_u = g_h@W1a^T + b1  (bf16 out)
// MODE 2: g_v = g_h@W1b^T       (bf16 out)
template <int MODE>
__device__ __forceinline__ void ld_tiles(int kbi, int m0, int n0, int tid, int M,
                                         const float* __restrict__ B1,
                                         const float* __restrict__ B2, int ldb,
                                         float4& a0, float4& a1, float4& b0, float4& b1v) {
    int hf = kbi >> 4;
    int kb = (kbi & 15) * 16;
    const float* A = (MODE == 0 && hf == 1) ? g_h : ((MODE == 0) ? g_agg : g_h);
    const float* B = hf ? B2 : B1;
    {
        int t = tid, row = t >> 2, kc = (t & 3) << 2;
        int gm = m0 + row;
        a0 = (gm < M) ? *(const float4*)(A + (size_t)gm * HID + kb + kc)
                      : make_float4(0.f, 0.f, 0.f, 0.f);
        b0 = *(const float4*)(B + (size_t)(n0 + row) * ldb + kb + kc);
    }
    {
        int t = tid + 256, row = t >> 2, kc = (t & 3) << 2;
        int gm = m0 + row;
        a1 = (gm < M) ? *(const float4*)(A + (size_t)gm * HID + kb + kc)
                      : make_float4(0.f, 0.f, 0.f, 0.f);
        b1v = *(const float4*)(B + (size_t)(n0 + row) * ldb + kb + kc);
    }
}

template <int MODE>
__global__ __launch_bounds__(256, 2) void k_gemm(
    const float* __restrict__ B1, const float* __restrict__ B2, int ldb,
    const float* __restrict__ bias, int M)
{
    constexpr int LDS = 20;
    constexpr int NKB = (MODE == 0) ? 32 : 16;

    __shared__ unsigned As[2][128][LDS];
    __shared__ unsigned Bs[2][128][LDS];
    __shared__ float s_sum[128], s_sq[128];

    int tid = threadIdx.x;
    int lane = tid & 31;
    int g = lane >> 2;
    int tg = lane & 3;
    int warp = tid >> 5;
    int wm = (warp & 1) * 64;
    int wn = (warp >> 1) * 32;
    int m0 = blockIdx.x * 128;
    int n0 = blockIdx.y * 128;

    if (MODE == 0 && tid < 128) { s_sum[tid] = 0.f; s_sq[tid] = 0.f; }

    float acc[4][4][4];
#pragma unroll
    for (int i = 0; i < 4; i++)
#pragma unroll
        for (int j = 0; j < 4; j++)
#pragma unroll
            for (int v = 0; v < 4; v++) acc[i][j][v] = 0.f;

    int r0s = tid >> 2, kc0 = (tid & 3) << 2;
    int r1s = (tid + 256) >> 2;

    float4 a0, a1, b0, b1v;
    ld_tiles<MODE>(0, m0, n0, tid, M, B1, B2, ldb, a0, a1, b0, b1v);
    As[0][r0s][kc0 + 0] = f2tf(a0.x); As[0][r0s][kc0 + 1] = f2tf(a0.y);
    As[0][r0s][kc0 + 2] = f2tf(a0.z); As[0][r0s][kc0 + 3] = f2tf(a0.w);
    As[0][r1s][kc0 + 0] = f2tf(a1.x); As[0][r1s][kc0 + 1] = f2tf(a1.y);
    As[0][r1s][kc0 + 2] = f2tf(a1.z); As[0][r1s][kc0 + 3] = f2tf(a1.w);
    Bs[0][r0s][kc0 + 0] = f2tf(b0.x); Bs[0][r0s][kc0 + 1] = f2tf(b0.y);
    Bs[0][r0s][kc0 + 2] = f2tf(b0.z); Bs[0][r0s][kc0 + 3] = f2tf(b0.w);
    Bs[0][r1s][kc0 + 0] = f2tf(b1v.x); Bs[0][r1s][kc0 + 1] = f2tf(b1v.y);
    Bs[0][r1s][kc0 + 2] = f2tf(b1v.z); Bs[0][r1s][kc0 + 3] = f2tf(b1v.w);
    __syncthreads();

    for (int kbi = 0; kbi < NKB; kbi++) {
        int cur = kbi & 1, nxt = cur ^ 1;
        if (kbi + 1 < NKB)
            ld_tiles<MODE>(kbi + 1, m0, n0, tid, M, B1, B2, ldb, a0, a1, b0, b1v);
#pragma unroll
        for (int kk = 0; kk < 16; kk += 8) {
            unsigned afr[4][4];
#pragma unroll
            for (int mt = 0; mt < 4; mt++) {
                int m = wm + mt * 16;
                afr[mt][0] = As[cur][m + g][kk + tg];
                afr[mt][1] = As[cur][m + g + 8][kk + tg];
                afr[mt][2] = As[cur][m + g][kk + tg + 4];
                afr[mt][3] = As[cur][m + g + 8][kk + tg + 4];
            }
            unsigned bfr[4][2];
#pragma unroll
            for (int nt = 0; nt < 4; nt++) {
                int n = wn + nt * 8;
                bfr[nt][0] = Bs[cur][n + g][kk + tg];
                bfr[nt][1] = Bs[cur][n + g][kk + tg + 4];
            }
#pragma unroll
            for (int mt = 0; mt < 4; mt++)
#pragma unroll
                for (int nt = 0; nt < 4; nt++)
                    mma_tf32(acc[mt][nt], afr[mt], bfr[nt]);
        }
        if (kbi + 1 < NKB) {
            As[nxt][r0s][kc0 + 0] = f2tf(a0.x); As[nxt][r0s][kc0 + 1] = f2tf(a0.y);
            As[nxt][r0s][kc0 + 2] = f2tf(a0.z); As[nxt][r0s][kc0 + 3] = f2tf(a0.w);
            As[nxt][r1s][kc0 + 0] = f2tf(a1.x); As[nxt][r1s][kc0 + 1] = f2tf(a1.y);
            As[nxt][r1s][kc0 + 2] = f2tf(a1.z); As[nxt][r1s][kc0 + 3] = f2tf(a1.w);
            Bs[nxt][r0s][kc0 + 0] = f2tf(b0.x); Bs[nxt][r0s][kc0 + 1] = f2tf(b0.y);
            Bs[nxt][r0s][kc0 + 2] = f2tf(b0.z); Bs[nxt][r0s][kc0 + 3] = f2tf(b0.w);
            Bs[nxt][r1s][kc0 + 0] = f2tf(b1v.x); Bs[nxt][r1s][kc0 + 1] = f2tf(b1v.y);
            Bs[nxt][r1s][kc0 + 2] = f2tf(b1v.z); Bs[nxt][r1s][kc0 + 3] = f2tf(b1v.w);
        }
        __syncthreads();
    }

    // epilogue
    float ls[4][2], lq[4][2];
    if (MODE == 0) {
#pragma unroll
        for (int nt = 0; nt < 4; nt++) { ls[nt][0] = ls[nt][1] = lq[nt][0] = lq[nt][1] = 0.f; }
    }
#pragma unroll
    for (int mt = 0; mt < 4; mt++) {
        int r0 = m0 + wm + mt * 16 + g;
#pragma unroll
        for (int nt = 0; nt < 4; nt++) {
            int col = n0 + wn + nt * 8 + tg * 2;
            float bb0 = bias[col], bb1 = bias[col + 1];
            float c0 = acc[mt][nt][0] + bb0, c1 = acc[mt][nt][1] + bb1;
            float c2 = acc[mt][nt][2] + bb0, c3 = acc[mt][nt][3] + bb1;
            if (MODE == 0) {
                if (r0 < M) {
                    *(float2*)(g_out + (size_t)r0 * HID + col) = make_float2(c0, c1);
                    ls[nt][0] += c0; lq[nt][0] += c0 * c0;
                    ls[nt][1] += c1; lq[nt][1] += c1 * c1;
                }
                if (r0 + 8 < M) {
                    *(float2*)(g_out + (size_t)(r0 + 8) * HID + col) = make_float2(c2, c3);
                    ls[nt][0] += c2; lq[nt][0] += c2 * c2;
                    ls[nt][1] += c3; lq[nt][1] += c3 * c3;
                }
            } else {
                __nv_bfloat16* Cb = (MODE == 1) ? g_u : g_v;
                if (r0 < M)
                    *(unsigned*)(Cb + (size_t)r0 * HID + col) = f2bf2(c0, c1);
                if (r0 + 8 < M)
                    *(unsigned*)(Cb + (size_t)(r0 + 8) * HID + col) = f2bf2(c2, c3);
            }
        }
    }
    if (MODE == 0) {
        // reduce over g lanes (stride-4 within warp), then smem, then global
#pragma unroll
        for (int nt = 0; nt < 4; nt++) {
#pragma unroll
            for (int p = 0; p < 2; p++) {
                float s = ls[nt][p], q = lq[nt][p];
#pragma unroll
                for (int off = 4; off < 32; off <<= 1) {
                    s += __shfl_xor_sync(0xffffffffu, s, off);
                    q += __shfl_xor_sync(0xffffffffu, q, off);
                }
                if (g == 0) {
                    int lc = wn + nt * 8 + tg * 2 + p;
                    atomicAdd(&s_sum[lc], s);
                    atomicAdd(&s_sq[lc], q);
                }
            }
        }
        __syncthreads();
        if (tid < 128) {
            atomicAdd(&g_bnsum[n0 + tid], s_sum[tid]);
            atomicAdd(&g_bnsq[n0 + tid], s_sq[tid]);
        }
    }
}

// ---------------- BN finalize ----------------
__global__ void k_bnfin(const float* __restrict__ gamma, const float* __restrict__ beta) {
    int c = threadIdx.x;
    float mean = g_bnsum[c] * (1.f / NN);
    float var = g_bnsq[c] * (1.f / NN) - mean * mean;
    float inv = rsqrtf(var + EPSV);
    float sc = gamma[c] * inv;
    g_scale[c] = sc;
    g_shift[c] = beta[c] - mean * sc;
}

// h += relu(out * scale + shift); also refresh bf16 copy
__global__ void k_update() {
    int i = blockIdx.x * blockDim.x + threadIdx.x;
    if (i >= NN * (HID / 4)) return;
    int c4 = (i & (HID / 4 - 1)) * 4;
    float4 o = ((const float4*)g_out)[i];
    float4 sc = *(const float4*)(g_scale + c4);
    float4 sh = *(const float4*)(g_shift + c4);
    float4 h = ((const float4*)g_h)[i];
    h.x += fmaxf(o.x * sc.x + sh.x, 0.f);
    h.y += fmaxf(o.y * sc.y + sh.y, 0.f);
    h.z += fmaxf(o.z * sc.z + sh.z, 0.f);
    h.w += fmaxf(o.w * sc.w + sh.w, 0.f);
    ((float4*)g_h)[i] = h;
    uint2 pk;
    pk.x = f2bf2(h.x, h.y);
    pk.y = f2bf2(h.z, h.w);
    ((uint2*)g_hb)[i] = pk;
}

// ---------------- fused edge kernel (double-buffered) ----------------
__global__ __launch_bounds__(256, 2) void k_edge(
    const float* __restrict__ W2, const float* __restrict__ b2,
    const float* __restrict__ W3, const float* __restrict__ b3,
    const int* __restrict__ src, const int* __restrict__ dst,
    float* __restrict__ out)
{
    constexpr int LDS = 20;
    __shared__ unsigned As[2][64][LDS];
    __shared__ unsigned Bs[2][256][LDS];
    __shared__ int rs[64], rd[64];
    __shared__ float lg[64];

    int tid = threadIdx.x;
    int lane = tid & 31;
    int g = lane >> 2;
    int tg = lane & 3;
    int warp = tid >> 5;
    int wm = (warp & 1) * 32;
    int wn = (warp >> 1) * 64;
    int m0 = blockIdx.x * 64;

    if (tid < 64) {
        int e = m0 + tid;
        rs[tid] = (e < NE) ? src[e] : 0;
        lg[tid] = 0.f;
    } else if (tid < 128) {
        int e = m0 + tid - 64;
        rd[tid - 64] = (e < NE) ? dst[e] : 0;
    }
    __syncthreads();

    float acc[2][8][4];
#pragma unroll
    for (int i = 0; i < 2; i++)
#pragma unroll
        for (int j = 0; j < 8; j++)
#pragma unroll
            for (int v = 0; v < 4; v++) acc[i][j][v] = 0.f;

    int arow = tid >> 2, akc = (tid & 3) << 2;
    const __nv_bfloat16* up = g_u + (size_t)rs[arow] * HID + akc;
    const __nv_bfloat16* vp = g_v + (size_t)rd[arow] * HID + akc;

    float4 av;
    float4 bv[4];
    {
        uint2 uu = *(const uint2*)up;
        uint2 vv = *(const uint2*)vp;
        float2 u0 = bf2f(uu.x), u1 = bf2f(uu.y);
        float2 v0 = bf2f(vv.x), v1 = bf2f(vv.y);
        av = make_float4(fmaxf(u0.x + v0.x, 0.f), fmaxf(u0.y + v0.y, 0.f),
                         fmaxf(u1.x + v1.x, 0.f), fmaxf(u1.y + v1.y, 0.f));
#pragma unroll
        for (int it = 0; it < 4; it++) {
            int t = tid + it * 256, row = t >> 2, kc = (t & 3) << 2;
            bv[it] = *(const float4*)(W2 + (size_t)row * HID + kc);
        }
    }
    As[0][arow][akc + 0] = f2tf(av.x); As[0][arow][akc + 1] = f2tf(av.y);
    As[0][arow][akc + 2] = f2tf(av.z); As[0][arow][akc + 3] = f2tf(av.w);
#pragma unroll
    for (int it = 0; it < 4; it++) {
        int t = tid + it * 256, row = t >> 2, kc = (t & 3) << 2;
        Bs[0][row][kc + 0] = f2tf(bv[it].x); Bs[0][row][kc + 1] = f2tf(bv[it].y);
        Bs[0][row][kc + 2] = f2tf(bv[it].z); Bs[0][row][kc + 3] = f2tf(bv[it].w);
    }
    __syncthreads();

    for (int kbi = 0; kbi < 16; kbi++) {
        int cur = kbi & 1, nxt = cur ^ 1;
        if (kbi + 1 < 16) {
            int kb = (kbi + 1) * 16;
            uint2 uu = *(const uint2*)(up + kb);
            uint2 vv = *(const uint2*)(vp + kb);
            float2 u0 = bf2f(uu.x), u1 = bf2f(uu.y);
            float2 v0 = bf2f(vv.x), v1 = bf2f(vv.y);
            av = make_float4(fmaxf(u0.x + v0.x, 0.f), fmaxf(u0.y + v0.y, 0.f),
                             fmaxf(u1.x + v1.x, 0.f), fmaxf(u1.y + v1.y, 0.f));
#pragma unroll
            for (int it = 0; it < 4; it++) {
                int t = tid + it * 256, row = t >> 2, kc = (t & 3) << 2;
                bv[it] = *(const float4*)(W2 + (size_t)row * HID + kb + kc);
            }
        }
#pragma unroll
        for (int kk = 0; kk < 16; kk += 8) {
            unsigned afr[2][4];
#pragma unroll
            for (int mt = 0; mt < 2; mt++) {
                int m = wm + mt * 16;
                afr[mt][0] = As[cur][m + g][kk + tg];
                afr[mt][1] = As[cur][m + g + 8][kk + tg];
                afr[mt][2] = As[cur][m + g][kk + tg + 4];
                afr[mt][3] = As[cur][m + g + 8][kk + tg + 4];
            }
            unsigned bfr[8][2];
#pragma unroll
            for (int nt = 0; nt < 8; nt++) {
                int n = wn + nt * 8;
                bfr[nt][0] = Bs[cur][n + g][kk + tg];
                bfr[nt][1] = Bs[cur][n + g][kk + tg + 4];
            }
#pragma unroll
            for (int mt = 0; mt < 2; mt++)
#pragma unroll
                for (int nt = 0; nt < 8; nt++)
                    mma_tf32(acc[mt][nt], afr[mt], bfr[nt]);
        }
        if (kbi + 1 < 16) {
            As[nxt][arow][akc + 0] = f2tf(av.x); As[nxt][arow][akc + 1] = f2tf(av.y);
            As[nxt][arow][akc + 2] = f2tf(av.z); As[nxt][arow][akc + 3] = f2tf(av.w);
#pragma unroll
            for (int it = 0; it < 4; it++) {
                int t = tid + it * 256, row = t >> 2, kc = (t & 3) << 2;
                Bs[nxt][row][kc + 0] = f2tf(bv[it].x); Bs[nxt][row][kc + 1] = f2tf(bv[it].y);
                Bs[nxt][row][kc + 2] = f2tf(bv[it].z); Bs[nxt][row][kc + 3] = f2tf(bv[it].w);
            }
        }
        __syncthreads();
    }

    // epilogue: z2 = relu(acc + b2), dot with W3, reduce, sigmoid
#pragma unroll
    for (int mt = 0; mt < 2; mt++) {
        int rl = wm + mt * 16 + g;
        float p0 = 0.f, p1 = 0.f;
#pragma unroll
        for (int nt = 0; nt < 8; nt++) {
            int col = wn + nt * 8 + tg * 2;
            float w3a = W3[col], w3b = W3[col + 1];
            float b2a = b2[col], b2b = b2[col + 1];
            p0 += fmaxf(acc[mt][nt][0] + b2a, 0.f) * w3a
                + fmaxf(acc[mt][nt][1] + b2b, 0.f) * w3b;
            p1 += fmaxf(acc[mt][nt][2] + b2a, 0.f) * w3a
                + fmaxf(acc[mt][nt][3] + b2b, 0.f) * w3b;
        }
        p0 += __shfl_xor_sync(0xffffffffu, p0, 1);
        p0 += __shfl_xor_sync(0xffffffffu, p0, 2);
        p1 += __shfl_xor_sync(0xffffffffu, p1, 1);
        p1 += __shfl_xor_sync(0xffffffffu, p1, 2);
        if (tg == 0) {
            atomicAdd(&lg[rl], p0);
            atomicAdd(&lg[rl + 8], p1);
        }
    }
    __syncthreads();
    if (tid < 64) {
        int e = m0 + tid;
        if (e < NE) out[e] = 1.f / (1.f + expf(-(lg[tid] + b3[0])));
    }
}

// ---------------- launch ----------------
extern "C" void kernel_launch(void* const* d_in, const int* in_sizes, int n_in,
                              void* d_out, int out_size) {
    (void)in_sizes; (void)n_in; (void)out_size;
    const float* x     = (const float*)d_in[0];
    const int*   ei    = (const int*)d_in[1];
    const float* W_in  = (const float*)d_in[2];
    const float* Wrel  = (const float*)d_in[3];
    const float* brel  = (const float*)d_in[4];
    const float* Wroot = (const float*)d_in[5];
    const float* gamma = (const float*)d_in[6];
    const float* beta  = (const float*)d_in[7];
    const float* W1    = (const float*)d_in[8];
    const float* b1    = (const float*)d_in[9];
    const float* W2    = (const float*)d_in[10];
    const float* b2    = (const float*)d_in[11];
    const float* W3    = (const float*)d_in[12];
    const float* b3    = (const float*)d_in[13];
    float* out = (float*)d_out;
    const int* src = ei;
    const int* dst = ei + NE;

    k_input<<<NN, 256>>>(x, W_in);

    k_count<<<(NE + 255) / 256, 256>>>(dst);
    k_scan<<<1, 1024>>>();
    k_fill<<<(NE + 255) / 256, 256>>>(src, dst);

    dim3 gemm_n((NN + 127) / 128, 2);
    for (int l = 0; l < NLAYERS; l++) {
        k_agg<<<(NN * 32 + 255) / 256, 256>>>();
        k_gemm<0><<<gemm_n, 256>>>(Wrel + (size_t)l * HID * HID,
                                   Wroot + (size_t)l * HID * HID, HID,
                                   brel + (size_t)l * HID, NN);
        k_bnfin<<<1, 256>>>(gamma + (size_t)l * HID, beta + (size_t)l * HID);
        k_update<<<(NN * (HID / 4) + 255) / 256, 256>>>();
    }

    // edge MLP: u = h@W1a^T + b1 (bf16), v = h@W1b^T (bf16), fused edge kernel
    k_gemm<1><<<gemm_n, 256>>>(W1, (const float*)0, 2 * HID, b1, NN);
    k_gemm<2><<<gemm_n, 256>>>(W1 + HID, (const float*)0, 2 * HID, g_zb, NN);
    k_edge<<<(NE + 63) / 64, 256>>>(W2, b2, W3, b3, src, dst, out);
}

// round 5
// speedup vs baseline: 3.2540x; 1.0753x over previous
#include <cuda_runtime.h>
#include <cuda_bf16.h>
#include <math.h>

#define NN 50000
#define NE 500000
#define HID 256
#define NLAYERS 15
#define EPSV 1e-5f

// ---------------- scratch (device globals: allocation-free) ----------------
__device__ float g_h[(size_t)NN * HID];             // residual stream (fp32, update-only)
__device__ __nv_bfloat16 g_hb[(size_t)NN * HID];    // bf16 copy (gather + GEMM operand)
__device__ __nv_bfloat16 g_aggb[(size_t)NN * HID];  // neighborhood sums (bf16)
__device__ float g_out[(size_t)NN * HID];           // pre-BN layer output (fp32)
__device__ __nv_bfloat16 g_u[(size_t)NN * HID];     // h @ W1a^T + b1 (bf16)
__device__ __nv_bfloat16 g_v[(size_t)NN * HID];     // h @ W1b^T (bf16)
__device__ __nv_bfloat16 g_w2b[HID * HID];          // W2 in bf16
__device__ int   g_rowptr[NN + 1];
__device__ int   g_cnt[NN];
__device__ int   g_col[NE];
__device__ float g_bnsum[HID];
__device__ float g_bnsq[HID];
__device__ float g_zb[HID];                         // zero bias (never written)

__device__ __forceinline__ float2 bf2f(unsigned u) {
    __nv_bfloat162 b = *(__nv_bfloat162*)&u;
    return make_float2(__bfloat162float(b.x), __bfloat162float(b.y));
}
__device__ __forceinline__ unsigned f2bf2(float a, float b) {
    __nv_bfloat162 p = __floats2bfloat162_rn(a, b);
    return *(unsigned*)&p;
}
__device__ __forceinline__ unsigned f2tf(float f) {
    unsigned r;
    asm("cvt.rna.tf32.f32 %0, %1;" : "=r"(r) : "f"(f));
    return r;
}
__device__ __forceinline__ void mma_tf32(float* c, const unsigned* a, const unsigned* b) {
    asm volatile(
        "mma.sync.aligned.m16n8k8.row.col.f32.tf32.tf32.f32 "
        "{%0,%1,%2,%3}, {%4,%5,%6,%7}, {%8,%9}, {%0,%1,%2,%3};"
        : "+f"(c[0]), "+f"(c[1]), "+f"(c[2]), "+f"(c[3])
        : "r"(a[0]), "r"(a[1]), "r"(a[2]), "r"(a[3]), "r"(b[0]), "r"(b[1]));
}

// ---------------- input fc ----------------
__global__ void k_input(const float* __restrict__ x, const float* __restrict__ W_in) {
    int i = blockIdx.x;
    int c = threadIdx.x;
    if (c == 0) g_cnt[i] = 0;
    float x0 = x[2 * i], x1 = x[2 * i + 1];
    float v = x0 * W_in[2 * c] + x1 * W_in[2 * c + 1];
    g_h[(size_t)i * HID + c] = v;
    g_hb[(size_t)i * HID + c] = __float2bfloat16(v);
}

// ---------------- W2 -> bf16 ----------------
__global__ void k_prep(const float* __restrict__ W2) {
    int i = blockIdx.x * 256 + threadIdx.x;
    g_w2b[i] = __float2bfloat16(W2[i]);
}

// ---------------- CSR build ----------------
__global__ void k_count(const int* __restrict__ dst) {
    int i = blockIdx.x * blockDim.x + threadIdx.x;
    if (i < NE) atomicAdd(&g_cnt[dst[i]], 1);
}

__global__ void k_scan() {
    __shared__ int ws[32];
    int t = threadIdx.x;
    int lane = t & 31, wid = t >> 5;
    const int CH = (NN + 1023) / 1024;
    int base = t * CH;
    int loc = 0;
#pragma unroll 1
    for (int j = 0; j < CH; j++) {
        int i = base + j;
        if (i < NN) loc += g_cnt[i];
    }
    int v = loc;
#pragma unroll
    for (int off = 1; off < 32; off <<= 1) {
        int n = __shfl_up_sync(0xffffffffu, v, off);
        if (lane >= off) v += n;
    }
    if (lane == 31) ws[wid] = v;
    __syncthreads();
    if (wid == 0) {
        int w = ws[lane];
#pragma unroll
        for (int off = 1; off < 32; off <<= 1) {
            int n = __shfl_up_sync(0xffffffffu, w, off);
            if (lane >= off) w += n;
        }
        ws[lane] = w;
    }
    __syncthreads();
    int run = (v - loc) + (wid ? ws[wid - 1] : 0);
#pragma unroll 1
    for (int j = 0; j < CH; j++) {
        int i = base + j;
        if (i < NN) { g_rowptr[i] = run; run += g_cnt[i]; g_cnt[i] = 0; }
    }
    if (t == 1023) g_rowptr[NN] = ws[31];
}

__global__ void k_fill(const int* __restrict__ src, const int* __restrict__ dst) {
    int i = blockIdx.x * blockDim.x + threadIdx.x;
    if (i < NE) {
        int d = dst[i];
        int p = atomicAdd(&g_cnt[d], 1);
        g_col[g_rowptr[d] + p] = src[i];
    }
}

// ---------------- aggregation (bf16 gather, fp32 accumulate, bf16 store) ----------------
__global__ void k_agg() {
    if (blockIdx.x == 0 && threadIdx.x < HID) {
        g_bnsum[threadIdx.x] = 0.f;
        g_bnsq[threadIdx.x] = 0.f;
    }
    int w = (blockIdx.x * blockDim.x + threadIdx.x) >> 5;
    int lane = threadIdx.x & 31;
    if (w >= NN) return;
    int e0 = g_rowptr[w], e1 = g_rowptr[w + 1];
    float a[8];
#pragma unroll
    for (int i = 0; i < 8; i++) a[i] = 0.f;
    for (int e = e0; e < e1; e++) {
        int s = g_col[e];
        uint4 r = *(const uint4*)(g_hb + (size_t)s * HID + lane * 8);
        float2 f0 = bf2f(r.x), f1 = bf2f(r.y), f2 = bf2f(r.z), f3 = bf2f(r.w);
        a[0] += f0.x; a[1] += f0.y; a[2] += f1.x; a[3] += f1.y;
        a[4] += f2.x; a[5] += f2.y; a[6] += f3.x; a[7] += f3.y;
    }
    uint4 pk;
    pk.x = f2bf2(a[0], a[1]); pk.y = f2bf2(a[2], a[3]);
    pk.z = f2bf2(a[4], a[5]); pk.w = f2bf2(a[6], a[7]);
    *(uint4*)(g_aggb + (size_t)w * HID + lane * 8) = pk;
}

// ---------------- tf32 GEMM, bf16 A operand (double-buffered) ----------------
// MODE 0: g_out = g_aggb@Wrel^T + g_hb@Wroot^T + brel ; fused BN stats (fp32 out)
// MODE 1: g_u = g_hb@W1a^T + b1  (bf16 out)
// MODE 2: g_v = g_hb@W1b^T       (bf16 out)
template <int MODE>
__device__ __forceinline__ void ld_tiles(int kbi, int m0, int n0, int tid, int M,
                                         const float* __restrict__ B1,
                                         const float* __restrict__ B2, int ldb,
                                         uint4& aA, float4& b0, float4& b1v) {
    int hf = kbi >> 4;
    int kb = (kbi & 15) * 16;
    const __nv_bfloat16* A = (MODE == 0 && hf == 0) ? g_aggb : g_hb;
    const float* B = hf ? B2 : B1;
    int arow = tid >> 1, aoff = (tid & 1) * 8;
    int gm = m0 + arow;
    aA = (gm < M) ? *(const uint4*)(A + (size_t)gm * HID + kb + aoff)
                  : make_uint4(0u, 0u, 0u, 0u);
    {
        int t = tid, row = t >> 2, kc = (t & 3) << 2;
        b0 = *(const float4*)(B + (size_t)(n0 + row) * ldb + kb + kc);
    }
    {
        int t = tid + 256, row = t >> 2, kc = (t & 3) << 2;
        b1v = *(const float4*)(B + (size_t)(n0 + row) * ldb + kb + kc);
    }
}

template <int MODE>
__global__ __launch_bounds__(256, 2) void k_gemm(
    const float* __restrict__ B1, const float* __restrict__ B2, int ldb,
    const float* __restrict__ bias, int M)
{
    constexpr int LDS = 20;
    constexpr int NKB = (MODE == 0) ? 32 : 16;

    __shared__ unsigned As[2][128][LDS];
    __shared__ unsigned Bs[2][128][LDS];
    __shared__ float s_sum[128], s_sq[128];

    int tid = threadIdx.x;
    int lane = tid & 31;
    int g = lane >> 2;
    int tg = lane & 3;
    int warp = tid >> 5;
    int wm = (warp & 1) * 64;
    int wn = (warp >> 1) * 32;
    int m0 = blockIdx.x * 128;
    int n0 = blockIdx.y * 128;

    if (MODE == 0 && tid < 128) { s_sum[tid] = 0.f; s_sq[tid] = 0.f; }

    float acc[4][4][4];
#pragma unroll
    for (int i = 0; i < 4; i++)
#pragma unroll
        for (int j = 0; j < 4; j++)
#pragma unroll
            for (int v = 0; v < 4; v++) acc[i][j][v] = 0.f;

    int arow = tid >> 1, aoff = (tid & 1) * 8;
    int r0s = tid >> 2, kc0 = (tid & 3) << 2;
    int r1s = (tid + 256) >> 2;

    uint4 aA; float4 b0, b1v;
    ld_tiles<MODE>(0, m0, n0, tid, M, B1, B2, ldb, aA, b0, b1v);
#define COMMIT(buf)                                                           \
    As[buf][arow][aoff + 0] = aA.x << 16;                                     \
    As[buf][arow][aoff + 1] = aA.x & 0xffff0000u;                             \
    As[buf][arow][aoff + 2] = aA.y << 16;                                     \
    As[buf][arow][aoff + 3] = aA.y & 0xffff0000u;                             \
    As[buf][arow][aoff + 4] = aA.z << 16;                                     \
    As[buf][arow][aoff + 5] = aA.z & 0xffff0000u;                             \
    As[buf][arow][aoff + 6] = aA.w << 16;                                     \
    As[buf][arow][aoff + 7] = aA.w & 0xffff0000u;                             \
    Bs[buf][r0s][kc0 + 0] = f2tf(b0.x); Bs[buf][r0s][kc0 + 1] = f2tf(b0.y);   \
    Bs[buf][r0s][kc0 + 2] = f2tf(b0.z); Bs[buf][r0s][kc0 + 3] = f2tf(b0.w);   \
    Bs[buf][r1s][kc0 + 0] = f2tf(b1v.x); Bs[buf][r1s][kc0 + 1] = f2tf(b1v.y); \
    Bs[buf][r1s][kc0 + 2] = f2tf(b1v.z); Bs[buf][r1s][kc0 + 3] = f2tf(b1v.w);
    COMMIT(0)
    __syncthreads();

    for (int kbi = 0; kbi < NKB; kbi++) {
        int cur = kbi & 1, nxt = cur ^ 1;
        if (kbi + 1 < NKB)
            ld_tiles<MODE>(kbi + 1, m0, n0, tid, M, B1, B2, ldb, aA, b0, b1v);
#pragma unroll
        for (int kk = 0; kk < 16; kk += 8) {
            unsigned afr[4][4];
#pragma unroll
            for (int mt = 0; mt < 4; mt++) {
                int m = wm + mt * 16;
                afr[mt][0] = As[cur][m + g][kk + tg];
                afr[mt][1] = As[cur][m + g + 8][kk + tg];
                afr[mt][2] = As[cur][m + g][kk + tg + 4];
                afr[mt][3] = As[cur][m + g + 8][kk + tg + 4];
            }
            unsigned bfr[4][2];
#pragma unroll
            for (int nt = 0; nt < 4; nt++) {
                int n = wn + nt * 8;
                bfr[nt][0] = Bs[cur][n + g][kk + tg];
                bfr[nt][1] = Bs[cur][n + g][kk + tg + 4];
            }
#pragma unroll
            for (int mt = 0; mt < 4; mt++)
#pragma unroll
                for (int nt = 0; nt < 4; nt++)
                    mma_tf32(acc[mt][nt], afr[mt], bfr[nt]);
        }
        if (kbi + 1 < NKB) {
            COMMIT(nxt)
        }
        __syncthreads();
    }
#undef COMMIT

    // epilogue
    float ls[4][2], lq[4][2];
    if (MODE == 0) {
#pragma unroll
        for (int nt = 0; nt < 4; nt++) { ls[nt][0] = ls[nt][1] = lq[nt][0] = lq[nt][1] = 0.f; }
    }
#pragma unroll
    for (int mt = 0; mt < 4; mt++) {
        int r0 = m0 + wm + mt * 16 + g;
#pragma unroll
        for (int nt = 0; nt < 4; nt++) {
            int col = n0 + wn + nt * 8 + tg * 2;
            float bb0 = bias[col], bb1 = bias[col + 1];
            float c0 = acc[mt][nt][0] + bb0, c1 = acc[mt][nt][1] + bb1;
            float c2 = acc[mt][nt][2] + bb0, c3 = acc[mt][nt][3] + bb1;
            if (MODE == 0) {
                if (r0 < M) {
                    *(float2*)(g_out + (size_t)r0 * HID + col) = make_float2(c0, c1);
                    ls[nt][0] += c0; lq[nt][0] += c0 * c0;
                    ls[nt][1] += c1; lq[nt][1] += c1 * c1;
                }
                if (r0 + 8 < M) {
                    *(float2*)(g_out + (size_t)(r0 + 8) * HID + col) = make_float2(c2, c3);
                    ls[nt][0] += c2; lq[nt][0] += c2 * c2;
                    ls[nt][1] += c3; lq[nt][1] += c3 * c3;
                }
            } else {
                __nv_bfloat16* Cb = (MODE == 1) ? g_u : g_v;
                if (r0 < M)
                    *(unsigned*)(Cb + (size_t)r0 * HID + col) = f2bf2(c0, c1);
                if (r0 + 8 < M)
                    *(unsigned*)(Cb + (size_t)(r0 + 8) * HID + col) = f2bf2(c2, c3);
            }
        }
    }
    if (MODE == 0) {
#pragma unroll
        for (int nt = 0; nt < 4; nt++) {
#pragma unroll
            for (int p = 0; p < 2; p++) {
                float s = ls[nt][p], q = lq[nt][p];
#pragma unroll
                for (int off = 4; off < 32; off <<= 1) {
                    s += __shfl_xor_sync(0xffffffffu, s, off);
                    q += __shfl_xor_sync(0xffffffffu, q, off);
                }
                if (g == 0) {
                    int lc = wn + nt * 8 + tg * 2 + p;
                    atomicAdd(&s_sum[lc], s);
                    atomicAdd(&s_sq[lc], q);
                }
            }
        }
        __syncthreads();
        if (tid < 128) {
            atomicAdd(&g_bnsum[n0 + tid], s_sum[tid]);
            atomicAdd(&g_bnsq[n0 + tid], s_sq[tid]);
        }
    }
}

// ---------------- update (fused BN finalize): h += relu(out*scale+shift) ----------------
__global__ void k_update(const float* __restrict__ gamma, const float* __restrict__ beta) {
    __shared__ float s_sc[HID], s_sh[HID];
    int t = threadIdx.x;
    if (t < 64) {
        int c = t * 4;
        float4 s4 = *(const float4*)(g_bnsum + c);
        float4 q4 = *(const float4*)(g_bnsq + c);
        float4 gm = *(const float4*)(gamma + c);
        float4 bt = *(const float4*)(beta + c);
        float m, inv;
        m = s4.x * (1.f / NN); inv = rsqrtf(q4.x * (1.f / NN) - m * m + EPSV);
        s_sc[c + 0] = gm.x * inv; s_sh[c + 0] = bt.x - m * gm.x * inv;
        m = s4.y * (1.f / NN); inv = rsqrtf(q4.y * (1.f / NN) - m * m + EPSV);
        s_sc[c + 1] = gm.y * inv; s_sh[c + 1] = bt.y - m * gm.y * inv;
        m = s4.z * (1.f / NN); inv = rsqrtf(q4.z * (1.f / NN) - m * m + EPSV);
        s_sc[c + 2] = gm.z * inv; s_sh[c + 2] = bt.z - m * gm.z * inv;
        m = s4.w * (1.f / NN); inv = rsqrtf(q4.w * (1.f / NN) - m * m + EPSV);
        s_sc[c + 3] = gm.w * inv; s_sh[c + 3] = bt.w - m * gm.w * inv;
    }
    __syncthreads();
    int i = blockIdx.x * blockDim.x + t;
    if (i >= NN * (HID / 4)) return;
    int c4 = (i & (HID / 4 - 1)) * 4;
    float4 o = ((const float4*)g_out)[i];
    float4 sc = *(const float4*)(s_sc + c4);
    float4 sh = *(const float4*)(s_sh + c4);
    float4 h = ((const float4*)g_h)[i];
    h.x += fmaxf(o.x * sc.x + sh.x, 0.f);
    h.y += fmaxf(o.y * sc.y + sh.y, 0.f);
    h.z += fmaxf(o.z * sc.z + sh.z, 0.f);
    h.w += fmaxf(o.w * sc.w + sh.w, 0.f);
    ((float4*)g_h)[i] = h;
    uint2 pk;
    pk.x = f2bf2(h.x, h.y);
    pk.y = f2bf2(h.z, h.w);
    ((uint2*)g_hb)[i] = pk;
}

// ---------------- fused edge kernel: 128 edges/block, 512 threads ----------------
__global__ __launch_bounds__(512, 1) void k_edge(
    const float* __restrict__ b2, const float* __restrict__ W3,
    const float* __restrict__ b3,
    const int* __restrict__ src, const int* __restrict__ dst,
    float* __restrict__ out)
{
    constexpr int LDS = 20;
    __shared__ unsigned As[2][128][LDS];
    __shared__ unsigned Bs[2][256][LDS];
    __shared__ int rs[128], rd[128];
    __shared__ float lg[128];

    int tid = threadIdx.x;
    int lane = tid & 31;
    int g = lane >> 2;
    int tg = lane & 3;
    int warp = tid >> 5;
    int wm = (warp & 3) * 32;
    int wn = (warp >> 2) * 64;
    int m0 = blockIdx.x * 128;

    if (tid < 128) {
        int e = m0 + tid;
        rs[tid] = (e < NE) ? src[e] : 0;
        lg[tid] = 0.f;
    } else if (tid < 256) {
        int e = m0 + tid - 128;
        rd[tid - 128] = (e < NE) ? dst[e] : 0;
    }
    __syncthreads();

    float acc[2][8][4];
#pragma unroll
    for (int i = 0; i < 2; i++)
#pragma unroll
        for (int j = 0; j < 8; j++)
#pragma unroll
            for (int v = 0; v < 4; v++) acc[i][j][v] = 0.f;

    int arow = tid >> 2, akc = (tid & 3) << 2;     // A: 4 elems/thread
    int brow = tid >> 1, bkc = (tid & 1) * 8;      // B: 8 elems/thread
    const __nv_bfloat16* up = g_u + (size_t)rs[arow] * HID + akc;
    const __nv_bfloat16* vp = g_v + (size_t)rd[arow] * HID + akc;

    float4 av; uint4 bw;
    {
        uint2 uu = *(const uint2*)up;
        uint2 vv = *(const uint2*)vp;
        float2 u0 = bf2f(uu.x), u1 = bf2f(uu.y);
        float2 v0 = bf2f(vv.x), v1 = bf2f(vv.y);
        av = make_float4(fmaxf(u0.x + v0.x, 0.f), fmaxf(u0.y + v0.y, 0.f),
                         fmaxf(u1.x + v1.x, 0.f), fmaxf(u1.y + v1.y, 0.f));
        bw = *(const uint4*)(g_w2b + (size_t)brow * HID + bkc);
    }
#define ECOMMIT(buf)                                                    \
    As[buf][arow][akc + 0] = f2tf(av.x);                                \
    As[buf][arow][akc + 1] = f2tf(av.y);                                \
    As[buf][arow][akc + 2] = f2tf(av.z);                                \
    As[buf][arow][akc + 3] = f2tf(av.w);                                \
    Bs[buf][brow][bkc + 0] = bw.x << 16;                                \
    Bs[buf][brow][bkc + 1] = bw.x & 0xffff0000u;                        \
    Bs[buf][brow][bkc + 2] = bw.y << 16;                                \
    Bs[buf][brow][bkc + 3] = bw.y & 0xffff0000u;                        \
    Bs[buf][brow][bkc + 4] = bw.z << 16;                                \
    Bs[buf][brow][bkc + 5] = bw.z & 0xffff0000u;                        \
    Bs[buf][brow][bkc + 6] = bw.w << 16;                                \
    Bs[buf][brow][bkc + 7] = bw.w & 0xffff0000u;
    ECOMMIT(0)
    __syncthreads();

    for (int kbi = 0; kbi < 16; kbi++) {
        int cur = kbi & 1, nxt = cur ^ 1;
        if (kbi + 1 < 16) {
            int kb = (kbi + 1) * 16;
            uint2 uu = *(const uint2*)(up + kb);
            uint2 vv = *(const uint2*)(vp + kb);
            float2 u0 = bf2f(uu.x), u1 = bf2f(uu.y);
            float2 v0 = bf2f(vv.x), v1 = bf2f(vv.y);
            av = make_float4(fmaxf(u0.x + v0.x, 0.f), fmaxf(u0.y + v0.y, 0.f),
                             fmaxf(u1.x + v1.x, 0.f), fmaxf(u1.y + v1.y, 0.f));
            bw = *(const uint4*)(g_w2b + (size_t)brow * HID + kb + bkc);
        }
#pragma unroll
        for (int kk = 0; kk < 16; kk += 8) {
            unsigned afr[2][4];
#pragma unroll
            for (int mt = 0; mt < 2; mt++) {
                int m = wm + mt * 16;
                afr[mt][0] = As[cur][m + g][kk + tg];
                afr[mt][1] = As[cur][m + g + 8][kk + tg];
                afr[mt][2] = As[cur][m + g][kk + tg + 4];
                afr[mt][3] = As[cur][m + g + 8][kk + tg + 4];
            }
            unsigned bfr[8][2];
#pragma unroll
            for (int nt = 0; nt < 8; nt++) {
                int n = wn + nt * 8;
                bfr[nt][0] = Bs[cur][n + g][kk + tg];
                bfr[nt][1] = Bs[cur][n + g][kk + tg + 4];
            }
#pragma unroll
            for (int mt = 0; mt < 2; mt++)
#pragma unroll
                for (int nt = 0; nt < 8; nt++)
                    mma_tf32(acc[mt][nt], afr[mt], bfr[nt]);
        }
        if (kbi + 1 < 16) {
            ECOMMIT(nxt)
        }
        __syncthreads();
    }
#undef ECOMMIT

    // epilogue: z2 = relu(acc + b2), dot with W3, reduce, sigmoid
#pragma unroll
    for (int mt = 0; mt < 2; mt++) {
        int rl = wm + mt * 16 + g;
        float p0 = 0.f, p1 = 0.f;
#pragma unroll
        for (int nt = 0; nt < 8; nt++) {
            int col = wn + nt * 8 + tg * 2;
            float w3a = W3[col], w3b = W3[col + 1];
            float b2a = b2[col], b2b = b2[col + 1];
            p0 += fmaxf(acc[mt][nt][0] + b2a, 0.f) * w3a
                + fmaxf(acc[mt][nt][1] + b2b, 0.f) * w3b;
            p1 += fmaxf(acc[mt][nt][2] + b2a, 0.f) * w3a
                + fmaxf(acc[mt][nt][3] + b2b, 0.f) * w3b;
        }
        p0 += __shfl_xor_sync(0xffffffffu, p0, 1);
        p0 += __shfl_xor_sync(0xffffffffu, p0, 2);
        p1 += __shfl_xor_sync(0xffffffffu, p1, 1);
        p1 += __shfl_xor_sync(0xffffffffu, p1, 2);
        if (tg == 0) {
            atomicAdd(&lg[rl], p0);
            atomicAdd(&lg[rl + 8], p1);
        }
    }
    __syncthreads();
    if (tid < 128) {
        int e = m0 + tid;
        if (e < NE) out[e] = 1.f / (1.f + expf(-(lg[tid] + b3[0])));
    }
}

// ---------------- launch ----------------
extern "C" void kernel_launch(void* const* d_in, const int* in_sizes, int n_in,
                              void* d_out, int out_size) {
    (void)in_sizes; (void)n_in; (void)out_size;
    const float* x     = (const float*)d_in[0];
    const int*   ei    = (const int*)d_in[1];
    const float* W_in  = (const float*)d_in[2];
    const float* Wrel  = (const float*)d_in[3];
    const float* brel  = (const float*)d_in[4];
    const float* Wroot = (const float*)d_in[5];
    const float* gamma = (const float*)d_in[6];
    const float* beta  = (const float*)d_in[7];
    const float* W1    = (const float*)d_in[8];
    const float* b1    = (const float*)d_in[9];
    const float* W2    = (const float*)d_in[10];
    const float* b2    = (const float*)d_in[11];
    const float* W3    = (const float*)d_in[12];
    const float* b3    = (const float*)d_in[13];
    float* out = (float*)d_out;
    const int* src = ei;
    const int* dst = ei + NE;

    k_input<<<NN, 256>>>(x, W_in);
    k_prep<<<256, 256>>>(W2);

    k_count<<<(NE + 255) / 256, 256>>>(dst);
    k_scan<<<1, 1024>>>();
    k_fill<<<(NE + 255) / 256, 256>>>(src, dst);

    dim3 gemm_n((NN + 127) / 128, 2);
    for (int l = 0; l < NLAYERS; l++) {
        k_agg<<<(NN * 32 + 255) / 256, 256>>>();
        k_gemm<0><<<gemm_n, 256>>>(Wrel + (size_t)l * HID * HID,
                                   Wroot + (size_t)l * HID * HID, HID,
                                   brel + (size_t)l * HID, NN);
        k_update<<<(NN * (HID / 4) + 255) / 256, 256>>>(gamma + (size_t)l * HID,
                                                        beta + (size_t)l * HID);
    }

    // edge MLP: u = h@W1a^T + b1 (bf16), v = h@W1b^T (bf16), fused edge kernel
    k_gemm<1><<<gemm_n, 256>>>(W1, (const float*)0, 2 * HID, b1, NN);
    k_gemm<2><<<gemm_n, 256>>>(W1 + HID, (const float*)0, 2 * HID, g_zb, NN);
    k_edge<<<(NE + 127) / 128, 512>>>(b2, W3, b3, src, dst, out);
}